// round 3
// baseline (speedup 1.0000x reference)
#include <cuda_runtime.h>

#define T_STEPS 512
#define BATCH   256
#define HID     256
#define G3      768   // 3*HID

// ---------------- static scratch (no allocations allowed) ----------------
__device__ float    g_gi[(size_t)T_STEPS * G3 * BATCH];    // [t][g][b]  384 MB
__device__ float    g_hs[(size_t)T_STEPS * BATCH * HID];   // [t][b][j]  128 MB
__device__ unsigned g_flags[256];

// ---------------- helpers ----------------
__device__ __forceinline__ void ffma2(unsigned long long& d,
                                      unsigned long long a,
                                      unsigned long long b) {
    asm("fma.rn.f32x2 %0, %1, %2, %0;" : "+l"(d) : "l"(a), "l"(b));
}
__device__ __forceinline__ float2 upk(unsigned long long v) {
    float2 f;
    asm("mov.b64 {%0,%1}, %2;" : "=f"(f.x), "=f"(f.y) : "l"(v));
    return f;
}
__device__ __forceinline__ float sigm(float x) {
    return 1.0f / (1.0f + __expf(-x));
}

// ---------------- reset barrier flags ----------------
__global__ void reset_kernel() {
    if (threadIdx.x < 256) g_flags[threadIdx.x] = 0u;
}

// ---------------- phase 0: gi[t][g][b] = sum_i w_ih[g][i]*x[b][t][i] + b_ih[g] ----------------
// grid (512, 6, 2), block 256. SMEM: w^T [64][132] + x^T [64][132]
__global__ void __launch_bounds__(256) input_proj_kernel(
    const float* __restrict__ x, const float* __restrict__ w_ih,
    const float* __restrict__ b_ih) {
    extern __shared__ float sm[];
    float* wsm = sm;              // wsm[i*132 + g_local]
    float* xsm = sm + 64 * 132;   // xsm[i*132 + b_local]

    const int t  = blockIdx.x;
    const int g0 = blockIdx.y * 128;
    const int b0 = blockIdx.z * 128;
    const int tid = threadIdx.x;

    // load + transpose w_ih tile: 128 rows x 64
#pragma unroll
    for (int it = 0; it < 8; it++) {
        int f  = tid + 256 * it;       // 0..2047 float4 slots
        int gg = f >> 4, i4 = f & 15;
        float4 v = *(const float4*)(w_ih + (size_t)(g0 + gg) * 64 + i4 * 4);
        wsm[(i4 * 4 + 0) * 132 + gg] = v.x;
        wsm[(i4 * 4 + 1) * 132 + gg] = v.y;
        wsm[(i4 * 4 + 2) * 132 + gg] = v.z;
        wsm[(i4 * 4 + 3) * 132 + gg] = v.w;
    }
    // load + transpose x tile: 128 rows (b) x 64 (i)
#pragma unroll
    for (int it = 0; it < 8; it++) {
        int f  = tid + 256 * it;
        int bb = f >> 4, i4 = f & 15;
        float4 v = *(const float4*)(x + ((size_t)(b0 + bb) * T_STEPS + t) * 64 + i4 * 4);
        xsm[(i4 * 4 + 0) * 132 + bb] = v.x;
        xsm[(i4 * 4 + 1) * 132 + bb] = v.y;
        xsm[(i4 * 4 + 2) * 132 + bb] = v.z;
        xsm[(i4 * 4 + 3) * 132 + bb] = v.w;
    }
    __syncthreads();

    const int tg = tid & 15, tb = tid >> 4;
    const int gl = tg * 8, bl = tb * 8;

    float acc[64];
#pragma unroll
    for (int i = 0; i < 64; i++) acc[i] = 0.0f;

#pragma unroll 2
    for (int k = 0; k < 64; k++) {
        float4 wa = *(const float4*)(wsm + k * 132 + gl);
        float4 wb = *(const float4*)(wsm + k * 132 + gl + 4);
        float4 xa = *(const float4*)(xsm + k * 132 + bl);
        float4 xb = *(const float4*)(xsm + k * 132 + bl + 4);
        float wr[8] = {wa.x, wa.y, wa.z, wa.w, wb.x, wb.y, wb.z, wb.w};
        float xr[8] = {xa.x, xa.y, xa.z, xa.w, xb.x, xb.y, xb.z, xb.w};
#pragma unroll
        for (int gg = 0; gg < 8; gg++)
#pragma unroll
            for (int bb = 0; bb < 8; bb++)
                acc[gg * 8 + bb] += wr[gg] * xr[bb];
    }

#pragma unroll
    for (int gg = 0; gg < 8; gg++) {
        float bias = __ldg(b_ih + g0 + gl + gg);
        float* o = g_gi + ((size_t)t * G3 + (g0 + gl + gg)) * BATCH + b0 + bl;
        float4 o1 = make_float4(acc[gg * 8 + 0] + bias, acc[gg * 8 + 1] + bias,
                                acc[gg * 8 + 2] + bias, acc[gg * 8 + 3] + bias);
        float4 o2 = make_float4(acc[gg * 8 + 4] + bias, acc[gg * 8 + 5] + bias,
                                acc[gg * 8 + 6] + bias, acc[gg * 8 + 7] + bias);
        *(float4*)o       = o1;
        *(float4*)(o + 4) = o2;
    }
}

// ---------------- phase 1: persistent GRU recurrence ----------------
// grid (8,16), block 128. Block (gb,gj): batch tile b0=gb*32 (32 rows),
// hidden tile j0=gj*16 (16 units -> 48 gate rows). Weights cached in SMEM.
__global__ void __launch_bounds__(128) gru_rec_kernel(
    const float* __restrict__ w_hh, const float* __restrict__ b_hh) {
    extern __shared__ float sm[];
    float* ws   = sm;                 // [48][256]  gate-row r = g*16+jj
    float* h_s  = sm + 48 * 256;      // [32][260]  (padded)
    float* gh_s = h_s + 32 * 260;     // [48][33]

    const int tid  = threadIdx.x;
    const int lane = tid & 31;
    const int warp = tid >> 5;
    const int gb = blockIdx.x;        // 0..7
    const int gj = blockIdx.y;        // 0..15
    const int bid = gj * 8 + gb;      // 0..127
    const int b0 = gb * 32;
    const int j0 = gj * 16;

    // preload weight rows: r = gate*16 + jj  <-  w_hh[gate*256 + j0 + jj][:]
#pragma unroll
    for (int it = 0; it < 24; it++) {
        int f4 = tid + 128 * it;          // 0..3071 float4 slots
        int r = f4 >> 6, k4 = f4 & 63;
        int gate = r >> 4, jj = r & 15;
        float4 v = __ldg((const float4*)(w_hh +
                     ((size_t)(gate * 256 + j0 + jj)) * 256 + k4 * 4));
        *(float4*)(ws + r * 256 + k4 * 4) = v;
    }
    // combine-stage biases: jj_c = warp*4 + i
    float bhr[4], bhz[4], bhn[4];
#pragma unroll
    for (int i = 0; i < 4; i++) {
        int j = j0 + warp * 4 + i;
        bhr[i] = __ldg(b_hh + j);
        bhz[i] = __ldg(b_hh + 256 + j);
        bhn[i] = __ldg(b_hh + 512 + j);
    }
    __syncthreads();

    for (int t = 0; t < T_STEPS; t++) {
        // ---- load h tile [32 x 256] into SMEM (zeros at t=0) ----
        if (t == 0) {
#pragma unroll
            for (int it = 0; it < 16; it++) {
                int f = tid + 128 * it;  int row = f >> 6, k4 = f & 63;
                *(float4*)(h_s + row * 260 + k4 * 4) = make_float4(0.f, 0.f, 0.f, 0.f);
            }
        } else {
            const float4* src = (const float4*)(g_hs +
                                ((size_t)(t - 1) * BATCH + b0) * HID);
#pragma unroll
            for (int it = 0; it < 16; it++) {
                int f = tid + 128 * it;  int row = f >> 6, k4 = f & 63;
                float4 v = __ldcg(src + row * 64 + k4);
                *(float4*)(h_s + row * 260 + k4 * 4) = v;
            }
        }
        __syncthreads();

        // ---- gh[b][r] = sum_k ws[r][k] * h[b][k], f32x2 packed over k ----
        unsigned long long acc[12];
#pragma unroll
        for (int i = 0; i < 12; i++) acc[i] = 0ULL;

        const ulonglong2* hrow = (const ulonglong2*)(h_s + lane * 260);
#pragma unroll 2
        for (int k4 = 0; k4 < 64; k4++) {
            ulonglong2 hv = hrow[k4];
            ulonglong2 wv[12];
#pragma unroll
            for (int i = 0; i < 12; i++)
                wv[i] = ((const ulonglong2*)(ws + (4 * i + warp) * 256))[k4];
#pragma unroll
            for (int i = 0; i < 12; i++) ffma2(acc[i], wv[i].x, hv.x);
#pragma unroll
            for (int i = 0; i < 12; i++) ffma2(acc[i], wv[i].y, hv.y);
        }
#pragma unroll
        for (int i = 0; i < 12; i++) {
            float2 s = upk(acc[i]);
            gh_s[(4 * i + warp) * 33 + lane] = s.x + s.y;
        }
        __syncthreads();

        // ---- combine gates, write h_new to g_hs[t] ----
        const size_t giBase = (size_t)t * G3 * BATCH;
#pragma unroll
        for (int i = 0; i < 4; i++) {
            int jj = warp * 4 + i;
            int j  = j0 + jj;
            float ghr = gh_s[jj * 33 + lane];
            float ghz = gh_s[(16 + jj) * 33 + lane];
            float ghn = gh_s[(32 + jj) * 33 + lane];
            float gir = g_gi[giBase + (size_t)j * BATCH + b0 + lane];
            float giz = g_gi[giBase + (size_t)(256 + j) * BATCH + b0 + lane];
            float gin = g_gi[giBase + (size_t)(512 + j) * BATCH + b0 + lane];
            float r = sigm(gir + ghr + bhr[i]);
            float z = sigm(giz + ghz + bhz[i]);
            float n = tanhf(gin + r * (ghn + bhn[i]));
            float hp = h_s[lane * 260 + j];          // zeros at t=0
            float hnew = (1.0f - z) * n + z * hp;
            g_hs[((size_t)t * BATCH + b0 + lane) * HID + j] = hnew;
        }

        // ---- distributed-flag grid barrier ----
        __threadfence();
        __syncthreads();
        if (tid == 0) ((volatile unsigned*)g_flags)[bid] = (unsigned)(t + 1);
        {
            volatile unsigned* fl = g_flags;
            const unsigned tgt = (unsigned)(t + 1);
            while (fl[tid] < tgt) { __nanosleep(40); }
        }
        __syncthreads();
        __threadfence();
    }
}

// ---------------- phase 2: out[t*256+b] = dot(hs[t][b][:], w_out) + b_out ----------------
__global__ void __launch_bounds__(256) out_kernel(
    const float* __restrict__ w_out, const float* __restrict__ b_out,
    float* __restrict__ out) {
    __shared__ __align__(16) float wsm[256];
    const int tid = threadIdx.x;
    wsm[tid] = w_out[tid];
    __syncthreads();

    const int warp = tid >> 5, lane = tid & 31;
    const size_t gid = (size_t)blockIdx.x * 8 + warp;   // = t*256 + b
    const float* hrow = g_hs + gid * HID;

    float s = 0.0f;
#pragma unroll
    for (int kk = 0; kk < 2; kk++) {
        int k4 = lane + 32 * kk;
        float4 h = *(const float4*)(hrow + k4 * 4);
        float4 w = *(const float4*)(wsm + k4 * 4);
        s += h.x * w.x + h.y * w.y + h.z * w.z + h.w * w.w;
    }
#pragma unroll
    for (int o = 16; o; o >>= 1) s += __shfl_down_sync(0xffffffffu, s, o);
    if (lane == 0) out[gid] = s + __ldg(b_out);
}

// ---------------- launch ----------------
extern "C" void kernel_launch(void* const* d_in, const int* in_sizes, int n_in,
                              void* d_out, int out_size) {
    const float* x     = (const float*)d_in[0];
    const float* w_ih  = (const float*)d_in[1];
    const float* w_hh  = (const float*)d_in[2];
    const float* b_ih  = (const float*)d_in[3];
    const float* b_hh  = (const float*)d_in[4];
    const float* w_out = (const float*)d_in[5];
    const float* b_out = (const float*)d_in[6];
    float* out = (float*)d_out;

    const int smem_proj = 64 * 132 * 2 * sizeof(float);                   // 67584
    const int smem_rec  = (48 * 256 + 32 * 260 + 48 * 33) * sizeof(float); // 88768
    cudaFuncSetAttribute(input_proj_kernel,
        cudaFuncAttributeMaxDynamicSharedMemorySize, smem_proj);
    cudaFuncSetAttribute(gru_rec_kernel,
        cudaFuncAttributeMaxDynamicSharedMemorySize, smem_rec);

    reset_kernel<<<1, 256>>>();
    input_proj_kernel<<<dim3(512, 6, 2), 256, smem_proj>>>(x, w_ih, b_ih);
    gru_rec_kernel<<<dim3(8, 16), 128, smem_rec>>>(w_hh, b_hh);
    out_kernel<<<16384, 256>>>(w_out, b_out, out);
}

// round 6
// speedup vs baseline: 1.2716x; 1.2716x over previous
#include <cuda_runtime.h>

#define T_STEPS 512
#define BATCH   256
#define HID     256
#define G3      768   // 3*HID

// ---------------- static scratch (no allocations allowed) ----------------
__device__ float    g_gi[(size_t)T_STEPS * G3 * BATCH];    // [t][g][b]
__device__ float    g_hs[(size_t)T_STEPS * BATCH * HID];   // [t][b][j]
__device__ float    g_hbuf[2][BATCH][HID];                 // ping-pong h
__device__ unsigned g_flags[128];

// ---------------- helpers ----------------
__device__ __forceinline__ void ffma2(unsigned long long& d,
                                      unsigned long long a,
                                      unsigned long long b) {
    asm("fma.rn.f32x2 %0, %1, %2, %0;" : "+l"(d) : "l"(a), "l"(b));
}
__device__ __forceinline__ unsigned long long pk2(float s) {
    unsigned long long d;
    asm("mov.b64 %0, {%1,%1};" : "=l"(d) : "f"(s));
    return d;
}
__device__ __forceinline__ float2 upk(unsigned long long v) {
    float2 f;
    asm("mov.b64 {%0,%1}, %2;" : "=f"(f.x), "=f"(f.y) : "l"(v));
    return f;
}
__device__ __forceinline__ float sigm(float x) {
    return 1.0f / (1.0f + __expf(-x));
}

// ---------------- reset barrier flags ----------------
__global__ void reset_kernel() {
    if (threadIdx.x < 128) g_flags[threadIdx.x] = 0u;
}

// ---------------- phase 0: gi[t][g][b] = sum_i w_ih[g][i]*x[b][t][i] + b_ih[g] ----------------
__global__ void __launch_bounds__(256) input_proj_kernel(
    const float* __restrict__ x, const float* __restrict__ w_ih,
    const float* __restrict__ b_ih) {
    extern __shared__ float sm[];
    float* wsm = sm;              // wsm[i*132 + g_local]
    float* xsm = sm + 64 * 132;   // xsm[i*132 + b_local]

    const int t  = blockIdx.x;
    const int g0 = blockIdx.y * 128;
    const int b0 = blockIdx.z * 128;
    const int tid = threadIdx.x;

#pragma unroll
    for (int it = 0; it < 8; it++) {
        int f  = tid + 256 * it;
        int gg = f >> 4, i4 = f & 15;
        float4 v = *(const float4*)(w_ih + (size_t)(g0 + gg) * 64 + i4 * 4);
        wsm[(i4 * 4 + 0) * 132 + gg] = v.x;
        wsm[(i4 * 4 + 1) * 132 + gg] = v.y;
        wsm[(i4 * 4 + 2) * 132 + gg] = v.z;
        wsm[(i4 * 4 + 3) * 132 + gg] = v.w;
    }
#pragma unroll
    for (int it = 0; it < 8; it++) {
        int f  = tid + 256 * it;
        int bb = f >> 4, i4 = f & 15;
        float4 v = *(const float4*)(x + ((size_t)(b0 + bb) * T_STEPS + t) * 64 + i4 * 4);
        xsm[(i4 * 4 + 0) * 132 + bb] = v.x;
        xsm[(i4 * 4 + 1) * 132 + bb] = v.y;
        xsm[(i4 * 4 + 2) * 132 + bb] = v.z;
        xsm[(i4 * 4 + 3) * 132 + bb] = v.w;
    }
    __syncthreads();

    const int tg = tid & 15, tb = tid >> 4;
    const int gl = tg * 8, bl = tb * 8;

    float acc[64];
#pragma unroll
    for (int i = 0; i < 64; i++) acc[i] = 0.0f;

#pragma unroll 2
    for (int k = 0; k < 64; k++) {
        float4 wa = *(const float4*)(wsm + k * 132 + gl);
        float4 wb = *(const float4*)(wsm + k * 132 + gl + 4);
        float4 xa = *(const float4*)(xsm + k * 132 + bl);
        float4 xb = *(const float4*)(xsm + k * 132 + bl + 4);
        float wr[8] = {wa.x, wa.y, wa.z, wa.w, wb.x, wb.y, wb.z, wb.w};
        float xr[8] = {xa.x, xa.y, xa.z, xa.w, xb.x, xb.y, xb.z, xb.w};
#pragma unroll
        for (int gg = 0; gg < 8; gg++)
#pragma unroll
            for (int bb = 0; bb < 8; bb++)
                acc[gg * 8 + bb] += wr[gg] * xr[bb];
    }

#pragma unroll
    for (int gg = 0; gg < 8; gg++) {
        float bias = __ldg(b_ih + g0 + gl + gg);
        float* o = g_gi + ((size_t)t * G3 + (g0 + gl + gg)) * BATCH + b0 + bl;
        float4 o1 = make_float4(acc[gg * 8 + 0] + bias, acc[gg * 8 + 1] + bias,
                                acc[gg * 8 + 2] + bias, acc[gg * 8 + 3] + bias);
        float4 o2 = make_float4(acc[gg * 8 + 4] + bias, acc[gg * 8 + 5] + bias,
                                acc[gg * 8 + 6] + bias, acc[gg * 8 + 7] + bias);
        *(float4*)o       = o1;
        *(float4*)(o + 4) = o2;
    }
}

// ---------------- phase 1: persistent GRU recurrence (register-tiled) ----------------
// grid (8,16), block 128. Block: batch tile 32 (b0), hidden tile 16 (j0).
// Thread (ri 0..15, bi 0..7): owns hidden unit j0+ri (all 3 gates) x 4 batches.
// Weight rows stored gate-interleaved: ws row 3*jloc+gate. h_s stored [k][b].
// Barrier is GROUP-LOCAL: only the 16 blocks sharing a batch tile sync.
#define WSTRIDE 268   // floats per ws row (pad for conflict-free LDS.128)

__global__ void __launch_bounds__(128) gru_rec_kernel(
    const float* __restrict__ w_hh, const float* __restrict__ b_hh) {
    extern __shared__ float sm[];
    float* ws  = sm;                    // [48][WSTRIDE]
    float* h_s = sm + 48 * WSTRIDE;     // [256][32]  (k-major)

    const int tid = threadIdx.x;
    const int ri  = tid & 15;           // hidden unit within tile
    const int bi  = tid >> 4;           // batch quad 0..7
    const int grp = blockIdx.x;         // batch tile 0..7
    const int jt  = blockIdx.y;         // hidden tile 0..15
    const int b0  = grp * 32;
    const int j0  = jt * 16;

    // preload gate-interleaved weight rows: r = 3*jloc + gate
#pragma unroll
    for (int it = 0; it < 24; it++) {
        int f4 = tid + 128 * it;            // 0..3071
        int r = f4 >> 6, k4 = f4 & 63;
        int jloc = r / 3, gate = r - 3 * jloc;
        float4 v = __ldg((const float4*)(w_hh +
                     ((size_t)(gate * 256 + j0 + jloc)) * 256 + k4 * 4));
        *(float4*)(ws + r * WSTRIDE + k4 * 4) = v;
    }
    const int j = j0 + ri;
    const float br = __ldg(b_hh + j);
    const float bz = __ldg(b_hh + 256 + j);
    const float bn = __ldg(b_hh + 512 + j);
    __syncthreads();

    const float4* wr0 = (const float4*)(ws + (3 * ri + 0) * WSTRIDE);
    const float4* wr1 = (const float4*)(ws + (3 * ri + 1) * WSTRIDE);
    const float4* wr2 = (const float4*)(ws + (3 * ri + 2) * WSTRIDE);
    const ulonglong2* hp = ((const ulonglong2*)h_s) + bi;   // hp[k*8 + bi]

    const int fb = tid & 31;        // fill: batch row
    const int fk = tid >> 5;        // fill: k quarter 0..3

    for (int t = 0; t < T_STEPS; t++) {
        // ---- prefetch gi for this thread's outputs (DRAM, hides under GEMM) ----
        const float* giB = g_gi + (size_t)t * G3 * BATCH;
        float4 gir = __ldcs((const float4*)(giB + (size_t)j * BATCH + b0 + 4 * bi));
        float4 giz = __ldcs((const float4*)(giB + (size_t)(256 + j) * BATCH + b0 + 4 * bi));
        float4 gin = __ldcs((const float4*)(giB + (size_t)(512 + j) * BATCH + b0 + 4 * bi));

        // ---- fill h_s[k][b] (transposed) from ping-pong buffer ----
        if (t == 0) {
#pragma unroll
            for (int kk = 0; kk < 16; kk++) {
                int kbase = fk * 64 + kk * 4;
#pragma unroll
                for (int i = 0; i < 4; i++) h_s[(kbase + i) * 32 + fb] = 0.0f;
            }
        } else {
            const float4* src = (const float4*)(&g_hbuf[t & 1][b0 + fb][0]) + fk * 16;
#pragma unroll
            for (int kk = 0; kk < 16; kk++) {
                float4 v = __ldcg(src + kk);
                int kbase = fk * 64 + kk * 4;
                h_s[(kbase + 0) * 32 + fb] = v.x;
                h_s[(kbase + 1) * 32 + fb] = v.y;
                h_s[(kbase + 2) * 32 + fb] = v.z;
                h_s[(kbase + 3) * 32 + fb] = v.w;
            }
        }
        __syncthreads();

        // ---- GEMM: 3 gate rows x 4 batches per thread, f32x2 over batch pairs ----
        unsigned long long aR0 = 0, aR1 = 0, aZ0 = 0, aZ1 = 0, aN0 = 0, aN1 = 0;
#pragma unroll 4
        for (int k4 = 0; k4 < 64; k4++) {
            const int kb = k4 * 4;
            ulonglong2 h0 = hp[(kb + 0) * 8];
            ulonglong2 h1 = hp[(kb + 1) * 8];
            ulonglong2 h2 = hp[(kb + 2) * 8];
            ulonglong2 h3 = hp[(kb + 3) * 8];
            float4 wa = wr0[k4];
            float4 wb = wr1[k4];
            float4 wc = wr2[k4];
            ffma2(aR0, pk2(wa.x), h0.x); ffma2(aR1, pk2(wa.x), h0.y);
            ffma2(aZ0, pk2(wb.x), h0.x); ffma2(aZ1, pk2(wb.x), h0.y);
            ffma2(aN0, pk2(wc.x), h0.x); ffma2(aN1, pk2(wc.x), h0.y);
            ffma2(aR0, pk2(wa.y), h1.x); ffma2(aR1, pk2(wa.y), h1.y);
            ffma2(aZ0, pk2(wb.y), h1.x); ffma2(aZ1, pk2(wb.y), h1.y);
            ffma2(aN0, pk2(wc.y), h1.x); ffma2(aN1, pk2(wc.y), h1.y);
            ffma2(aR0, pk2(wa.z), h2.x); ffma2(aR1, pk2(wa.z), h2.y);
            ffma2(aZ0, pk2(wb.z), h2.x); ffma2(aZ1, pk2(wb.z), h2.y);
            ffma2(aN0, pk2(wc.z), h2.x); ffma2(aN1, pk2(wc.z), h2.y);
            ffma2(aR0, pk2(wa.w), h3.x); ffma2(aR1, pk2(wa.w), h3.y);
            ffma2(aZ0, pk2(wb.w), h3.x); ffma2(aZ1, pk2(wb.w), h3.y);
            ffma2(aN0, pk2(wc.w), h3.x); ffma2(aN1, pk2(wc.w), h3.y);
        }

        // ---- thread-local gate combine ----
        float2 r01 = upk(aR0), r23 = upk(aR1);
        float2 z01 = upk(aZ0), z23 = upk(aZ1);
        float2 n01 = upk(aN0), n23 = upk(aN1);
        float accR[4] = {r01.x, r01.y, r23.x, r23.y};
        float accZ[4] = {z01.x, z01.y, z23.x, z23.y};
        float accN[4] = {n01.x, n01.y, n23.x, n23.y};
        float giRv[4] = {gir.x, gir.y, gir.z, gir.w};
        float giZv[4] = {giz.x, giz.y, giz.z, giz.w};
        float giNv[4] = {gin.x, gin.y, gin.z, gin.w};

        float* hbN = &g_hbuf[(t + 1) & 1][0][0];
        float* hsT = g_hs + (size_t)t * BATCH * HID;
#pragma unroll
        for (int m = 0; m < 4; m++) {
            int b = b0 + 4 * bi + m;
            float rg = sigm(giRv[m] + accR[m] + br);
            float zg = sigm(giZv[m] + accZ[m] + bz);
            float ng = tanhf(giNv[m] + rg * (accN[m] + bn));
            float hp_ = h_s[j * 32 + 4 * bi + m];          // zeros at t=0
            float hnew = (1.0f - zg) * ng + zg * hp_;
            __stcg(hbN + (size_t)b * HID + j, hnew);       // next-step exchange (L2)
            __stcs(hsT + (size_t)b * HID + j, hnew);       // history (DRAM, streaming)
        }

        // ---- group-local barrier (16 blocks sharing this batch tile) ----
        __threadfence();
        __syncthreads();
        if (tid == 0) ((volatile unsigned*)g_flags)[grp * 16 + jt] = (unsigned)(t + 1);
        {
            volatile unsigned* fl = g_flags + grp * 16;
            const unsigned tgt = (unsigned)(t + 1);
            while (fl[tid & 15] < tgt) { __nanosleep(20); }
        }
        __syncthreads();
    }
}

// ---------------- phase 2: out[t*256+b] = dot(hs[t][b][:], w_out) + b_out ----------------
__global__ void __launch_bounds__(256) out_kernel(
    const float* __restrict__ w_out, const float* __restrict__ b_out,
    float* __restrict__ out) {
    __shared__ __align__(16) float wsm[256];
    const int tid = threadIdx.x;
    wsm[tid] = w_out[tid];
    __syncthreads();

    const int warp = tid >> 5, lane = tid & 31;
    const size_t gid = (size_t)blockIdx.x * 8 + warp;   // = t*256 + b
    const float* hrow = g_hs + gid * HID;

    float s = 0.0f;
#pragma unroll
    for (int kk = 0; kk < 2; kk++) {
        int k4 = lane + 32 * kk;
        float4 h = *(const float4*)(hrow + k4 * 4);
        float4 w = *(const float4*)(wsm + k4 * 4);
        s += h.x * w.x + h.y * w.y + h.z * w.z + h.w * w.w;
    }
#pragma unroll
    for (int o = 16; o; o >>= 1) s += __shfl_down_sync(0xffffffffu, s, o);
    if (lane == 0) out[gid] = s + __ldg(b_out);
}

// ---------------- launch ----------------
extern "C" void kernel_launch(void* const* d_in, const int* in_sizes, int n_in,
                              void* d_out, int out_size) {
    const float* x     = (const float*)d_in[0];
    const float* w_ih  = (const float*)d_in[1];
    const float* w_hh  = (const float*)d_in[2];
    const float* b_ih  = (const float*)d_in[3];
    const float* b_hh  = (const float*)d_in[4];
    const float* w_out = (const float*)d_in[5];
    const float* b_out = (const float*)d_in[6];
    float* out = (float*)d_out;

    const int smem_proj = 64 * 132 * 2 * sizeof(float);                    // 67584
    const int smem_rec  = (48 * WSTRIDE + 256 * 32) * sizeof(float);       // 84224
    cudaFuncSetAttribute(input_proj_kernel,
        cudaFuncAttributeMaxDynamicSharedMemorySize, smem_proj);
    cudaFuncSetAttribute(gru_rec_kernel,
        cudaFuncAttributeMaxDynamicSharedMemorySize, smem_rec);

    reset_kernel<<<1, 128>>>();
    input_proj_kernel<<<dim3(512, 6, 2), 256, smem_proj>>>(x, w_ih, b_ih);
    gru_rec_kernel<<<dim3(8, 16), 128, smem_rec>>>(w_hh, b_hh);
    out_kernel<<<16384, 256>>>(w_out, b_out, out);
}

// round 7
// speedup vs baseline: 1.4520x; 1.1419x over previous
#include <cuda_runtime.h>

#define T_STEPS 512
#define BATCH   256
#define HID     256
#define G3      768   // 3*HID

// ---------------- static scratch (no allocations allowed) ----------------
__device__ float    g_gi[(size_t)T_STEPS * G3 * BATCH];    // [t][g][b]
__device__ float    g_hs[(size_t)T_STEPS * BATCH * HID];   // [t][b][j]
__device__ float    g_hbuf[2][BATCH][HID];                 // ping-pong h
__device__ unsigned g_flags[128];

// ---------------- helpers ----------------
__device__ __forceinline__ void ffma2(unsigned long long& d,
                                      unsigned long long a,
                                      unsigned long long b) {
    asm("fma.rn.f32x2 %0, %1, %2, %0;" : "+l"(d) : "l"(a), "l"(b));
}
__device__ __forceinline__ float2 upk(unsigned long long v) {
    float2 f;
    asm("mov.b64 {%0,%1}, %2;" : "=f"(f.x), "=f"(f.y) : "l"(v));
    return f;
}
__device__ __forceinline__ float sigm(float x) {
    return 1.0f / (1.0f + __expf(-x));
}

// ---------------- reset barrier flags ----------------
__global__ void reset_kernel() {
    if (threadIdx.x < 128) g_flags[threadIdx.x] = 0u;
}

// ---------------- phase 0: gi[t][g][b] = sum_i w_ih[g][i]*x[b][t][i] + b_ih[g] ----------------
__global__ void __launch_bounds__(256) input_proj_kernel(
    const float* __restrict__ x, const float* __restrict__ w_ih,
    const float* __restrict__ b_ih) {
    extern __shared__ float sm[];
    float* wsm = sm;              // wsm[i*132 + g_local]
    float* xsm = sm + 64 * 132;   // xsm[i*132 + b_local]

    const int t  = blockIdx.x;
    const int g0 = blockIdx.y * 128;
    const int b0 = blockIdx.z * 128;
    const int tid = threadIdx.x;

#pragma unroll
    for (int it = 0; it < 8; it++) {
        int f  = tid + 256 * it;
        int gg = f >> 4, i4 = f & 15;
        float4 v = *(const float4*)(w_ih + (size_t)(g0 + gg) * 64 + i4 * 4);
        wsm[(i4 * 4 + 0) * 132 + gg] = v.x;
        wsm[(i4 * 4 + 1) * 132 + gg] = v.y;
        wsm[(i4 * 4 + 2) * 132 + gg] = v.z;
        wsm[(i4 * 4 + 3) * 132 + gg] = v.w;
    }
#pragma unroll
    for (int it = 0; it < 8; it++) {
        int f  = tid + 256 * it;
        int bb = f >> 4, i4 = f & 15;
        float4 v = *(const float4*)(x + ((size_t)(b0 + bb) * T_STEPS + t) * 64 + i4 * 4);
        xsm[(i4 * 4 + 0) * 132 + bb] = v.x;
        xsm[(i4 * 4 + 1) * 132 + bb] = v.y;
        xsm[(i4 * 4 + 2) * 132 + bb] = v.z;
        xsm[(i4 * 4 + 3) * 132 + bb] = v.w;
    }
    __syncthreads();

    const int tg = tid & 15, tb = tid >> 4;
    const int gl = tg * 8, bl = tb * 8;

    float acc[64];
#pragma unroll
    for (int i = 0; i < 64; i++) acc[i] = 0.0f;

#pragma unroll 2
    for (int k = 0; k < 64; k++) {
        float4 wa = *(const float4*)(wsm + k * 132 + gl);
        float4 wb = *(const float4*)(wsm + k * 132 + gl + 4);
        float4 xa = *(const float4*)(xsm + k * 132 + bl);
        float4 xb = *(const float4*)(xsm + k * 132 + bl + 4);
        float wr[8] = {wa.x, wa.y, wa.z, wa.w, wb.x, wb.y, wb.z, wb.w};
        float xr[8] = {xa.x, xa.y, xa.z, xa.w, xb.x, xb.y, xb.z, xb.w};
#pragma unroll
        for (int gg = 0; gg < 8; gg++)
#pragma unroll
            for (int bb = 0; bb < 8; bb++)
                acc[gg * 8 + bb] += wr[gg] * xr[bb];
    }

#pragma unroll
    for (int gg = 0; gg < 8; gg++) {
        float bias = __ldg(b_ih + g0 + gl + gg);
        float* o = g_gi + ((size_t)t * G3 + (g0 + gl + gg)) * BATCH + b0 + bl;
        float4 o1 = make_float4(acc[gg * 8 + 0] + bias, acc[gg * 8 + 1] + bias,
                                acc[gg * 8 + 2] + bias, acc[gg * 8 + 3] + bias);
        float4 o2 = make_float4(acc[gg * 8 + 4] + bias, acc[gg * 8 + 5] + bias,
                                acc[gg * 8 + 6] + bias, acc[gg * 8 + 7] + bias);
        *(float4*)o       = o1;
        *(float4*)(o + 4) = o2;
    }
}

// ---------------- phase 1: persistent GRU recurrence ----------------
// grid (8,16), block 128. Block: batch tile 32 (b0), hidden tile 16 (j0).
// Thread (ri, bi): hidden unit j0+ri (3 gates) x 4 batches (b0+4bi..).
// f32x2 packed over K. Weights in per-thread interleaved SMEM chunks
// (12 floats = 3 gate-float4s per (k4,ri)): lane stride 48B -> conflict-free.
// h_s row-major [b][k] stride 260 -> straight float4 fill, conflict-free.
#define HSTRIDE 260

__global__ void __launch_bounds__(128) gru_rec_kernel(
    const float* __restrict__ w_hh, const float* __restrict__ b_hh) {
    extern __shared__ float sm[];
    float* w_il = sm;                     // [64*16][12]  48 KB
    float* h_s  = sm + 64 * 16 * 12;      // [32][HSTRIDE] 33.3 KB

    const int tid = threadIdx.x;
    const int ri  = tid & 15;             // hidden unit within tile
    const int bi  = tid >> 4;             // batch quad 0..7
    const int grp = blockIdx.x;           // batch tile 0..7
    const int jt  = blockIdx.y;           // hidden tile 0..15
    const int b0  = grp * 32;
    const int j0  = jt * 16;

    // ---- preload interleaved weights: dst float4 index f4 = chunk*3 + gate,
    //      chunk = k4*16 + rl;  src = w_hh[(gate*256 + j0 + rl)][k4*4..]
#pragma unroll
    for (int it = 0; it < 24; it++) {
        int f4 = tid + 128 * it;              // 0..3071
        int chunk = f4 / 3, g = f4 - 3 * chunk;
        int k4 = chunk >> 4, rl = chunk & 15;
        float4 v = __ldg((const float4*)(w_hh +
                     ((size_t)(g * 256 + j0 + rl)) * 256 + k4 * 4));
        *(float4*)(w_il + 4 * f4) = v;
    }
    const int j = j0 + ri;
    const float br = __ldg(b_hh + j);
    const float bz = __ldg(b_hh + 256 + j);
    const float bn = __ldg(b_hh + 512 + j);
    __syncthreads();

    const float* wbase = w_il + ri * 12;            // + k4*192 per step
    const float* hbase = h_s + (4 * bi) * HSTRIDE;  // rows m*HSTRIDE

    const int fb = tid & 31;          // fill: batch row
    const int fk = tid >> 5;          // fill: k quarter (16 float4)

    volatile unsigned* flg = g_flags + grp * 16;

    // prefetch gi(0)
    const float* giB = g_gi;
    float4 gir = __ldcs((const float4*)(giB + (size_t)j * BATCH + b0 + 4 * bi));
    float4 giz = __ldcs((const float4*)(giB + (size_t)(256 + j) * BATCH + b0 + 4 * bi));
    float4 gin = __ldcs((const float4*)(giB + (size_t)(512 + j) * BATCH + b0 + 4 * bi));

    for (int t = 0; t < T_STEPS; t++) {
        // ---- fill h_s[b][k] (direct copy, no transpose) ----
        if (t == 0) {
            float4 z4 = make_float4(0.f, 0.f, 0.f, 0.f);
#pragma unroll
            for (int kk = 0; kk < 16; kk++)
                *(float4*)(h_s + fb * HSTRIDE + fk * 64 + kk * 4) = z4;
        } else {
            const float4* src = (const float4*)(&g_hbuf[t & 1][b0 + fb][0]) + fk * 16;
            float4 v[16];
#pragma unroll
            for (int kk = 0; kk < 16; kk++) v[kk] = __ldcg(src + kk);
#pragma unroll
            for (int kk = 0; kk < 16; kk++)
                *(float4*)(h_s + fb * HSTRIDE + fk * 64 + kk * 4) = v[kk];
        }
        __syncthreads();

        // ---- GEMM: 3 gates x 4 batches per thread, f32x2 over K ----
        unsigned long long aR[4] = {0, 0, 0, 0};
        unsigned long long aZ[4] = {0, 0, 0, 0};
        unsigned long long aN[4] = {0, 0, 0, 0};
#pragma unroll 4
        for (int k4 = 0; k4 < 64; k4++) {
            const float* wp = wbase + k4 * 192;
            ulonglong2 wR = *(const ulonglong2*)(wp);
            ulonglong2 wZ = *(const ulonglong2*)(wp + 4);
            ulonglong2 wN = *(const ulonglong2*)(wp + 8);
#pragma unroll
            for (int m = 0; m < 4; m++) {
                ulonglong2 hv = *(const ulonglong2*)(hbase + m * HSTRIDE + k4 * 4);
                ffma2(aR[m], wR.x, hv.x); ffma2(aR[m], wR.y, hv.y);
                ffma2(aZ[m], wZ.x, hv.x); ffma2(aZ[m], wZ.y, hv.y);
                ffma2(aN[m], wN.x, hv.x); ffma2(aN[m], wN.y, hv.y);
            }
        }

        // ---- thread-local gate combine ----
        float giRv[4] = {gir.x, gir.y, gir.z, gir.w};
        float giZv[4] = {giz.x, giz.y, giz.z, giz.w};
        float giNv[4] = {gin.x, gin.y, gin.z, gin.w};

        float* hbN = &g_hbuf[(t + 1) & 1][0][0];
        float* hsT = g_hs + (size_t)t * BATCH * HID;
#pragma unroll
        for (int m = 0; m < 4; m++) {
            float2 r2 = upk(aR[m]);
            float2 z2 = upk(aZ[m]);
            float2 n2 = upk(aN[m]);
            int b = b0 + 4 * bi + m;
            float rg = sigm(giRv[m] + (r2.x + r2.y) + br);
            float zg = sigm(giZv[m] + (z2.x + z2.y) + bz);
            float ng = tanhf(giNv[m] + rg * ((n2.x + n2.y) + bn));
            float hp_ = h_s[(4 * bi + m) * HSTRIDE + j];    // zeros at t=0
            float hnew = (1.0f - zg) * ng + zg * hp_;
            __stcg(hbN + (size_t)b * HID + j, hnew);        // next-step exchange
            __stcs(hsT + (size_t)b * HID + j, hnew);        // history
        }

        // ---- publish, prefetch next gi under the wait, then acquire-poll ----
        __threadfence();
        __syncthreads();
        if (tid == 0)
            asm volatile("st.release.gpu.u32 [%0], %1;"
                         :: "l"((unsigned*)(g_flags + grp * 16 + jt)),
                            "r"((unsigned)(t + 1)) : "memory");

        if (t + 1 < T_STEPS) {
            const float* giN = g_gi + (size_t)(t + 1) * G3 * BATCH;
            gir = __ldcs((const float4*)(giN + (size_t)j * BATCH + b0 + 4 * bi));
            giz = __ldcs((const float4*)(giN + (size_t)(256 + j) * BATCH + b0 + 4 * bi));
            gin = __ldcs((const float4*)(giN + (size_t)(512 + j) * BATCH + b0 + 4 * bi));
        }

        {
            const unsigned tgt = (unsigned)(t + 1);
            const unsigned* myf = (const unsigned*)(g_flags + grp * 16 + (tid & 15));
            unsigned v;
            do {
                asm volatile("ld.acquire.gpu.u32 %0, [%1];"
                             : "=r"(v) : "l"(myf) : "memory");
            } while (v < tgt);
        }
        __syncthreads();
    }
}

// ---------------- phase 2: out[t*256+b] = dot(hs[t][b][:], w_out) + b_out ----------------
__global__ void __launch_bounds__(256) out_kernel(
    const float* __restrict__ w_out, const float* __restrict__ b_out,
    float* __restrict__ out) {
    __shared__ __align__(16) float wsm[256];
    const int tid = threadIdx.x;
    wsm[tid] = w_out[tid];
    __syncthreads();

    const int warp = tid >> 5, lane = tid & 31;
    const size_t gid = (size_t)blockIdx.x * 8 + warp;   // = t*256 + b
    const float* hrow = g_hs + gid * HID;

    float s = 0.0f;
#pragma unroll
    for (int kk = 0; kk < 2; kk++) {
        int k4 = lane + 32 * kk;
        float4 h = *(const float4*)(hrow + k4 * 4);
        float4 w = *(const float4*)(wsm + k4 * 4);
        s += h.x * w.x + h.y * w.y + h.z * w.z + h.w * w.w;
    }
#pragma unroll
    for (int o = 16; o; o >>= 1) s += __shfl_down_sync(0xffffffffu, s, o);
    if (lane == 0) out[gid] = s + __ldg(b_out);
}

// ---------------- launch ----------------
extern "C" void kernel_launch(void* const* d_in, const int* in_sizes, int n_in,
                              void* d_out, int out_size) {
    const float* x     = (const float*)d_in[0];
    const float* w_ih  = (const float*)d_in[1];
    const float* w_hh  = (const float*)d_in[2];
    const float* b_ih  = (const float*)d_in[3];
    const float* b_hh  = (const float*)d_in[4];
    const float* w_out = (const float*)d_in[5];
    const float* b_out = (const float*)d_in[6];
    float* out = (float*)d_out;

    const int smem_proj = 64 * 132 * 2 * sizeof(float);                  // 67584
    const int smem_rec  = (64 * 16 * 12 + 32 * HSTRIDE) * sizeof(float); // 82432
    cudaFuncSetAttribute(input_proj_kernel,
        cudaFuncAttributeMaxDynamicSharedMemorySize, smem_proj);
    cudaFuncSetAttribute(gru_rec_kernel,
        cudaFuncAttributeMaxDynamicSharedMemorySize, smem_rec);

    reset_kernel<<<1, 128>>>();
    input_proj_kernel<<<dim3(512, 6, 2), 256, smem_proj>>>(x, w_ih, b_ih);
    gru_rec_kernel<<<dim3(8, 16), 128, smem_rec>>>(w_hh, b_hh);
    out_kernel<<<16384, 256>>>(w_out, b_out, out);
}

// round 8
// speedup vs baseline: 2.0412x; 1.4058x over previous
#include <cuda_runtime.h>

#define T_STEPS 512
#define BATCH   256
#define HID     256
#define G3      768   // 3*HID

// ---------------- static scratch (no allocations allowed) ----------------
__device__ float    g_gi[(size_t)T_STEPS * G3 * BATCH];    // [t][g][b]
__device__ float    g_hs[(size_t)T_STEPS * BATCH * HID];   // [t][b][j]
__device__ unsigned g_cnt[8][32];                          // 1 counter/group, 128B apart

// ---------------- helpers ----------------
__device__ __forceinline__ void ffma2(unsigned long long& d,
                                      unsigned long long a,
                                      unsigned long long b) {
    asm("fma.rn.f32x2 %0, %1, %2, %0;" : "+l"(d) : "l"(a), "l"(b));
}
__device__ __forceinline__ unsigned long long pk2(float s) {
    unsigned long long d;
    asm("mov.b64 %0, {%1,%1};" : "=l"(d) : "f"(s));
    return d;
}
__device__ __forceinline__ float2 upk(unsigned long long v) {
    float2 f;
    asm("mov.b64 {%0,%1}, %2;" : "=f"(f.x), "=f"(f.y) : "l"(v));
    return f;
}
__device__ __forceinline__ float sigm(float x) {
    return 1.0f / (1.0f + __expf(-x));
}
__device__ __forceinline__ float fast_tanh(float x) {
    // 1 - 2/(e^{2x}+1); saturates correctly for |x| large
    float e = __expf(2.0f * x);
    return 1.0f - __fdividef(2.0f, e + 1.0f);
}

// ---------------- reset counters ----------------
__global__ void reset_kernel() {
    if (threadIdx.x < 8 * 32) ((unsigned*)g_cnt)[threadIdx.x] = 0u;
}

// ---------------- phase 0: gi[t][g][b] = sum_i w_ih[g][i]*x[b][t][i] + b_ih[g] ----------------
// f32x2 packed over batch pairs.
__global__ void __launch_bounds__(256) input_proj_kernel(
    const float* __restrict__ x, const float* __restrict__ w_ih,
    const float* __restrict__ b_ih) {
    extern __shared__ float sm[];
    float* wsm = sm;              // wsm[i*132 + g_local]
    float* xsm = sm + 64 * 132;   // xsm[i*132 + b_local]

    const int t  = blockIdx.x;
    const int g0 = blockIdx.y * 128;
    const int b0 = blockIdx.z * 128;
    const int tid = threadIdx.x;

#pragma unroll
    for (int it = 0; it < 8; it++) {
        int f  = tid + 256 * it;
        int gg = f >> 4, i4 = f & 15;
        float4 v = *(const float4*)(w_ih + (size_t)(g0 + gg) * 64 + i4 * 4);
        wsm[(i4 * 4 + 0) * 132 + gg] = v.x;
        wsm[(i4 * 4 + 1) * 132 + gg] = v.y;
        wsm[(i4 * 4 + 2) * 132 + gg] = v.z;
        wsm[(i4 * 4 + 3) * 132 + gg] = v.w;
    }
#pragma unroll
    for (int it = 0; it < 8; it++) {
        int f  = tid + 256 * it;
        int bb = f >> 4, i4 = f & 15;
        float4 v = *(const float4*)(x + ((size_t)(b0 + bb) * T_STEPS + t) * 64 + i4 * 4);
        xsm[(i4 * 4 + 0) * 132 + bb] = v.x;
        xsm[(i4 * 4 + 1) * 132 + bb] = v.y;
        xsm[(i4 * 4 + 2) * 132 + bb] = v.z;
        xsm[(i4 * 4 + 3) * 132 + bb] = v.w;
    }
    __syncthreads();

    const int tg = tid & 15, tb = tid >> 4;
    const int gl = tg * 8, bl = tb * 8;

    unsigned long long acc[32];   // [gg][pair]  pairs of adjacent b
#pragma unroll
    for (int i = 0; i < 32; i++) acc[i] = 0ULL;

#pragma unroll 2
    for (int k = 0; k < 64; k++) {
        float4 wa = *(const float4*)(wsm + k * 132 + gl);
        float4 wb = *(const float4*)(wsm + k * 132 + gl + 4);
        ulonglong2 x01 = *(const ulonglong2*)(xsm + k * 132 + bl);
        ulonglong2 x23 = *(const ulonglong2*)(xsm + k * 132 + bl + 4);
        float wr[8] = {wa.x, wa.y, wa.z, wa.w, wb.x, wb.y, wb.z, wb.w};
#pragma unroll
        for (int gg = 0; gg < 8; gg++) {
            unsigned long long wd = pk2(wr[gg]);
            ffma2(acc[gg * 4 + 0], wd, x01.x);
            ffma2(acc[gg * 4 + 1], wd, x01.y);
            ffma2(acc[gg * 4 + 2], wd, x23.x);
            ffma2(acc[gg * 4 + 3], wd, x23.y);
        }
    }

#pragma unroll
    for (int gg = 0; gg < 8; gg++) {
        float bias = __ldg(b_ih + g0 + gl + gg);
        float2 p0 = upk(acc[gg * 4 + 0]);
        float2 p1 = upk(acc[gg * 4 + 1]);
        float2 p2 = upk(acc[gg * 4 + 2]);
        float2 p3 = upk(acc[gg * 4 + 3]);
        float* o = g_gi + ((size_t)t * G3 + (g0 + gl + gg)) * BATCH + b0 + bl;
        *(float4*)o       = make_float4(p0.x + bias, p0.y + bias, p1.x + bias, p1.y + bias);
        *(float4*)(o + 4) = make_float4(p2.x + bias, p2.y + bias, p3.x + bias, p3.y + bias);
    }
}

// ---------------- phase 1: persistent GRU recurrence ----------------
// grid (16 jt, 8 grp) -> group members contiguous in linear block id.
// Block: batch tile 32 (b0), hidden tile 16 (j0). Thread (ri, bi): unit j0+ri
// (3 gates) x 4 batches. f32x2 over K. Weights in per-thread interleaved SMEM.
// Barrier: per-group padded counter, red.release publish, single acquire-poller.
#define HSTRIDE 260

__global__ void __launch_bounds__(128) gru_rec_kernel(
    const float* __restrict__ w_hh, const float* __restrict__ b_hh) {
    extern __shared__ float sm[];
    float* w_il = sm;                     // [64*16][12]  48 KB
    float* h_s  = sm + 64 * 16 * 12;      // [32][HSTRIDE] 33.3 KB

    const int tid = threadIdx.x;
    const int ri  = tid & 15;             // hidden unit within tile
    const int bi  = tid >> 4;             // batch quad 0..7
    const int jt  = blockIdx.x;           // hidden tile 0..15
    const int grp = blockIdx.y;           // batch group 0..7
    const int b0  = grp * 32;
    const int j0  = jt * 16;

    // ---- preload interleaved weights: f4 = (k4*16 + rl)*3 + gate ----
#pragma unroll
    for (int it = 0; it < 24; it++) {
        int f4 = tid + 128 * it;              // 0..3071
        int chunk = f4 / 3, g = f4 - 3 * chunk;
        int k4 = chunk >> 4, rl = chunk & 15;
        float4 v = __ldg((const float4*)(w_hh +
                     ((size_t)(g * 256 + j0 + rl)) * 256 + k4 * 4));
        *(float4*)(w_il + 4 * f4) = v;
    }
    const int j = j0 + ri;
    const float br = __ldg(b_hh + j);
    const float bz = __ldg(b_hh + 256 + j);
    const float bn = __ldg(b_hh + 512 + j);
    __syncthreads();

    const float* wbase = w_il + ri * 12;            // + k4*192 per step
    const float* hbase = h_s + (4 * bi) * HSTRIDE;  // rows m*HSTRIDE

    const int fb = tid & 31;          // fill: batch row
    const int fk = tid >> 5;          // fill: k quarter (16 float4)

    unsigned* cnt = &g_cnt[grp][0];

    // prefetch gi(0)
    const float* giB = g_gi;
    float4 gir = __ldcs((const float4*)(giB + (size_t)j * BATCH + b0 + 4 * bi));
    float4 giz = __ldcs((const float4*)(giB + (size_t)(256 + j) * BATCH + b0 + 4 * bi));
    float4 gin = __ldcs((const float4*)(giB + (size_t)(512 + j) * BATCH + b0 + 4 * bi));

    for (int t = 0; t < T_STEPS; t++) {
        // ---- fill h_s[b][k] from g_hs[t-1] (zeros at t=0) ----
        if (t == 0) {
            float4 z4 = make_float4(0.f, 0.f, 0.f, 0.f);
#pragma unroll
            for (int kk = 0; kk < 16; kk++)
                *(float4*)(h_s + fb * HSTRIDE + fk * 64 + kk * 4) = z4;
        } else {
            const float4* src = (const float4*)(g_hs +
                                ((size_t)(t - 1) * BATCH + b0 + fb) * HID) + fk * 16;
            float4 v[16];
#pragma unroll
            for (int kk = 0; kk < 16; kk++) v[kk] = __ldcg(src + kk);
#pragma unroll
            for (int kk = 0; kk < 16; kk++)
                *(float4*)(h_s + fb * HSTRIDE + fk * 64 + kk * 4) = v[kk];
        }
        __syncthreads();

        // ---- GEMM: 3 gates x 4 batches per thread, f32x2 over K ----
        unsigned long long aR[4] = {0, 0, 0, 0};
        unsigned long long aZ[4] = {0, 0, 0, 0};
        unsigned long long aN[4] = {0, 0, 0, 0};
#pragma unroll 4
        for (int k4 = 0; k4 < 64; k4++) {
            const float* wp = wbase + k4 * 192;
            ulonglong2 wR = *(const ulonglong2*)(wp);
            ulonglong2 wZ = *(const ulonglong2*)(wp + 4);
            ulonglong2 wN = *(const ulonglong2*)(wp + 8);
#pragma unroll
            for (int m = 0; m < 4; m++) {
                ulonglong2 hv = *(const ulonglong2*)(hbase + m * HSTRIDE + k4 * 4);
                ffma2(aR[m], wR.x, hv.x); ffma2(aR[m], wR.y, hv.y);
                ffma2(aZ[m], wZ.x, hv.x); ffma2(aZ[m], wZ.y, hv.y);
                ffma2(aN[m], wN.x, hv.x); ffma2(aN[m], wN.y, hv.y);
            }
        }

        // ---- thread-local gate combine + single h store (stays in L2) ----
        float giRv[4] = {gir.x, gir.y, gir.z, gir.w};
        float giZv[4] = {giz.x, giz.y, giz.z, giz.w};
        float giNv[4] = {gin.x, gin.y, gin.z, gin.w};

        float* hsT = g_hs + (size_t)t * BATCH * HID;
#pragma unroll
        for (int m = 0; m < 4; m++) {
            float2 r2 = upk(aR[m]);
            float2 z2 = upk(aZ[m]);
            float2 n2 = upk(aN[m]);
            int b = b0 + 4 * bi + m;
            float rg = sigm(giRv[m] + (r2.x + r2.y) + br);
            float zg = sigm(giZv[m] + (z2.x + z2.y) + bz);
            float ng = fast_tanh(giNv[m] + rg * ((n2.x + n2.y) + bn));
            float hp_ = h_s[(4 * bi + m) * HSTRIDE + j];    // zeros at t=0
            float hnew = (1.0f - zg) * ng + zg * hp_;
            __stcg(hsT + (size_t)b * HID + j, hnew);
        }

        if (t + 1 < T_STEPS) {
            // ---- publish: one release-reduction per block ----
            __threadfence();
            __syncthreads();
            if (tid == 0)
                asm volatile("red.release.gpu.global.add.u32 [%0], %1;"
                             :: "l"(cnt), "r"(1u) : "memory");

            // ---- prefetch next gi under the wait ----
            const float* giN = g_gi + (size_t)(t + 1) * G3 * BATCH;
            gir = __ldcs((const float4*)(giN + (size_t)j * BATCH + b0 + 4 * bi));
            giz = __ldcs((const float4*)(giN + (size_t)(256 + j) * BATCH + b0 + 4 * bi));
            gin = __ldcs((const float4*)(giN + (size_t)(512 + j) * BATCH + b0 + 4 * bi));

            // ---- single poller, then block-wide release via bar ----
            if (tid == 0) {
                const unsigned tgt = 16u * (unsigned)(t + 1);
                unsigned v;
                do {
                    asm volatile("ld.acquire.gpu.global.u32 %0, [%1];"
                                 : "=r"(v) : "l"(cnt) : "memory");
                } while (v < tgt);
            }
            __syncthreads();
        }
    }
}

// ---------------- phase 2: out[t*256+b] = dot(hs[t][b][:], w_out) + b_out ----------------
__global__ void __launch_bounds__(256) out_kernel(
    const float* __restrict__ w_out, const float* __restrict__ b_out,
    float* __restrict__ out) {
    __shared__ __align__(16) float wsm[256];
    const int tid = threadIdx.x;
    wsm[tid] = w_out[tid];
    __syncthreads();

    const int warp = tid >> 5, lane = tid & 31;
    const size_t gid = (size_t)blockIdx.x * 8 + warp;   // = t*256 + b
    const float* hrow = g_hs + gid * HID;

    float s = 0.0f;
#pragma unroll
    for (int kk = 0; kk < 2; kk++) {
        int k4 = lane + 32 * kk;
        float4 h = *(const float4*)(hrow + k4 * 4);
        float4 w = *(const float4*)(wsm + k4 * 4);
        s += h.x * w.x + h.y * w.y + h.z * w.z + h.w * w.w;
    }
#pragma unroll
    for (int o = 16; o; o >>= 1) s += __shfl_down_sync(0xffffffffu, s, o);
    if (lane == 0) out[gid] = s + __ldg(b_out);
}

// ---------------- launch ----------------
extern "C" void kernel_launch(void* const* d_in, const int* in_sizes, int n_in,
                              void* d_out, int out_size) {
    const float* x     = (const float*)d_in[0];
    const float* w_ih  = (const float*)d_in[1];
    const float* w_hh  = (const float*)d_in[2];
    const float* b_ih  = (const float*)d_in[3];
    const float* b_hh  = (const float*)d_in[4];
    const float* w_out = (const float*)d_in[5];
    const float* b_out = (const float*)d_in[6];
    float* out = (float*)d_out;

    const int smem_proj = 64 * 132 * 2 * sizeof(float);                  // 67584
    const int smem_rec  = (64 * 16 * 12 + 32 * HSTRIDE) * sizeof(float); // 82432
    cudaFuncSetAttribute(input_proj_kernel,
        cudaFuncAttributeMaxDynamicSharedMemorySize, smem_proj);
    cudaFuncSetAttribute(gru_rec_kernel,
        cudaFuncAttributeMaxDynamicSharedMemorySize, smem_rec);

    reset_kernel<<<1, 256>>>();
    input_proj_kernel<<<dim3(512, 6, 2), 256, smem_proj>>>(x, w_ih, b_ih);
    gru_rec_kernel<<<dim3(16, 8), 128, smem_rec>>>(w_hh, b_hh);
    out_kernel<<<16384, 256>>>(w_out, b_out, out);
}

// round 9
// speedup vs baseline: 2.5729x; 1.2604x over previous
#include <cuda_runtime.h>

#define T_STEPS 512
#define BATCH   256
#define HID     256
#define G3      768   // 3*HID

// ---------------- static scratch (no allocations allowed) ----------------
__device__ float    g_gi[(size_t)T_STEPS * G3 * BATCH];    // [t][g][b]
__device__ float    g_hs[(size_t)T_STEPS * BATCH * HID];   // [t][b][j]
__device__ unsigned g_cnt[8][32];                          // 1 counter/group, 128B apart

// ---------------- helpers ----------------
__device__ __forceinline__ void ffma2(unsigned long long& d,
                                      unsigned long long a,
                                      unsigned long long b) {
    asm("fma.rn.f32x2 %0, %1, %2, %0;" : "+l"(d) : "l"(a), "l"(b));
}
__device__ __forceinline__ unsigned long long pk2(float s) {
    unsigned long long d;
    asm("mov.b64 %0, {%1,%1};" : "=l"(d) : "f"(s));
    return d;
}
__device__ __forceinline__ float2 upk(unsigned long long v) {
    float2 f;
    asm("mov.b64 {%0,%1}, %2;" : "=f"(f.x), "=f"(f.y) : "l"(v));
    return f;
}
__device__ __forceinline__ float sigm(float x) {
    return 1.0f / (1.0f + __expf(-x));
}
__device__ __forceinline__ float fast_tanh(float x) {
    float e = __expf(2.0f * x);
    return 1.0f - __fdividef(2.0f, e + 1.0f);
}

// ---------------- reset counters ----------------
__global__ void reset_kernel() {
    if (threadIdx.x < 8 * 32) ((unsigned*)g_cnt)[threadIdx.x] = 0u;
}

// ---------------- phase 0: gi[t][g][b] = sum_i w_ih[g][i]*x[b][t][i] + b_ih[g] ----------------
__global__ void __launch_bounds__(256) input_proj_kernel(
    const float* __restrict__ x, const float* __restrict__ w_ih,
    const float* __restrict__ b_ih) {
    extern __shared__ float sm[];
    float* wsm = sm;              // wsm[i*132 + g_local]
    float* xsm = sm + 64 * 132;   // xsm[i*132 + b_local]

    const int t  = blockIdx.x;
    const int g0 = blockIdx.y * 128;
    const int b0 = blockIdx.z * 128;
    const int tid = threadIdx.x;

#pragma unroll
    for (int it = 0; it < 8; it++) {
        int f  = tid + 256 * it;
        int gg = f >> 4, i4 = f & 15;
        float4 v = *(const float4*)(w_ih + (size_t)(g0 + gg) * 64 + i4 * 4);
        wsm[(i4 * 4 + 0) * 132 + gg] = v.x;
        wsm[(i4 * 4 + 1) * 132 + gg] = v.y;
        wsm[(i4 * 4 + 2) * 132 + gg] = v.z;
        wsm[(i4 * 4 + 3) * 132 + gg] = v.w;
    }
#pragma unroll
    for (int it = 0; it < 8; it++) {
        int f  = tid + 256 * it;
        int bb = f >> 4, i4 = f & 15;
        float4 v = *(const float4*)(x + ((size_t)(b0 + bb) * T_STEPS + t) * 64 + i4 * 4);
        xsm[(i4 * 4 + 0) * 132 + bb] = v.x;
        xsm[(i4 * 4 + 1) * 132 + bb] = v.y;
        xsm[(i4 * 4 + 2) * 132 + bb] = v.z;
        xsm[(i4 * 4 + 3) * 132 + bb] = v.w;
    }
    __syncthreads();

    const int tg = tid & 15, tb = tid >> 4;
    const int gl = tg * 8, bl = tb * 8;

    unsigned long long acc[32];
#pragma unroll
    for (int i = 0; i < 32; i++) acc[i] = 0ULL;

#pragma unroll 2
    for (int k = 0; k < 64; k++) {
        float4 wa = *(const float4*)(wsm + k * 132 + gl);
        float4 wb = *(const float4*)(wsm + k * 132 + gl + 4);
        ulonglong2 x01 = *(const ulonglong2*)(xsm + k * 132 + bl);
        ulonglong2 x23 = *(const ulonglong2*)(xsm + k * 132 + bl + 4);
        float wr[8] = {wa.x, wa.y, wa.z, wa.w, wb.x, wb.y, wb.z, wb.w};
#pragma unroll
        for (int gg = 0; gg < 8; gg++) {
            unsigned long long wd = pk2(wr[gg]);
            ffma2(acc[gg * 4 + 0], wd, x01.x);
            ffma2(acc[gg * 4 + 1], wd, x01.y);
            ffma2(acc[gg * 4 + 2], wd, x23.x);
            ffma2(acc[gg * 4 + 3], wd, x23.y);
        }
    }

#pragma unroll
    for (int gg = 0; gg < 8; gg++) {
        float bias = __ldg(b_ih + g0 + gl + gg);
        float2 p0 = upk(acc[gg * 4 + 0]);
        float2 p1 = upk(acc[gg * 4 + 1]);
        float2 p2 = upk(acc[gg * 4 + 2]);
        float2 p3 = upk(acc[gg * 4 + 3]);
        float* o = g_gi + ((size_t)t * G3 + (g0 + gl + gg)) * BATCH + b0 + bl;
        *(float4*)o       = make_float4(p0.x + bias, p0.y + bias, p1.x + bias, p1.y + bias);
        *(float4*)(o + 4) = make_float4(p2.x + bias, p2.y + bias, p3.x + bias, p3.y + bias);
    }
}

// ---------------- phase 1: persistent GRU recurrence (split-K, conflict-free) ----------------
// grid (16 jt, 8 grp), block 256: (ri 0..15, bi 0..7, kh 0..1).
// Weights: w_il[(k4*3+gate)*16+ri] float4  -> gate-contiguous, conflict-free.
// h_s rows permuted: row = (b&3)*8 + (b>>2), stride 260 -> lane stride 4 banks.
// kh splits K in half; SMEM reduction; kh=0 does combine + stores.
#define HSTRIDE 260

__global__ void __launch_bounds__(256) gru_rec_kernel(
    const float* __restrict__ w_hh, const float* __restrict__ b_hh) {
    extern __shared__ float sm[];
    float* w_il  = sm;                       // 64*3*16 float4 = 48 KB
    float* h_s   = sm + 64 * 3 * 16 * 4;     // [32][HSTRIDE]   = 33.3 KB
    float* red_s = h_s + 32 * HSTRIDE;       // [12][132]       = 6.3 KB

    const int tid = threadIdx.x;
    const int ri  = tid & 15;
    const int bi  = (tid >> 4) & 7;
    const int kh  = tid >> 7;               // 0 or 1
    const int jt  = blockIdx.x;
    const int grp = blockIdx.y;
    const int b0  = grp * 32;
    const int j0  = jt * 16;

    // ---- preload weights, gate-contiguous: f4 = (k4*3 + g)*16 + rl ----
#pragma unroll
    for (int it = 0; it < 12; it++) {
        int f4 = tid + 256 * it;             // 0..3071
        int rl = f4 & 15;
        int g  = (f4 >> 4) % 3;
        int k4 = f4 / 48;
        float4 v = __ldg((const float4*)(w_hh +
                     ((size_t)(g * 256 + j0 + rl)) * 256 + k4 * 4));
        *(float4*)(w_il + 4 * f4) = v;
    }
    const int j = j0 + ri;
    const float br = __ldg(b_hh + j);
    const float bz = __ldg(b_hh + 256 + j);
    const float bn = __ldg(b_hh + 512 + j);
    __syncthreads();

    // GEMM pointers: this thread handles k4 in [kh*32, kh*32+32)
    const float* wbase = w_il + ((kh * 32 * 3) * 16 + ri) * 4;  // advance 192 floats/k4
    // h rows for (bi, m): row = m*8 + bi ; k offset = kh*128
    const float* hb0 = h_s + (0 * 8 + bi) * HSTRIDE + kh * 128;
    const float* hb1 = h_s + (1 * 8 + bi) * HSTRIDE + kh * 128;
    const float* hb2 = h_s + (2 * 8 + bi) * HSTRIDE + kh * 128;
    const float* hb3 = h_s + (3 * 8 + bi) * HSTRIDE + kh * 128;

    const int frow = tid & 31;               // fill: SMEM row
    const int fk   = tid >> 5;               // fill: 8 float4 group
    const int fsrc = 4 * (frow & 7) + (frow >> 3);   // global batch offset for row

    unsigned* cnt = &g_cnt[grp][0];

    // prefetch gi(0) (combine threads only)
    float4 gir, giz, gin;
    if (kh == 0) {
        const float* giB = g_gi;
        gir = __ldcs((const float4*)(giB + (size_t)j * BATCH + b0 + 4 * bi));
        giz = __ldcs((const float4*)(giB + (size_t)(256 + j) * BATCH + b0 + 4 * bi));
        gin = __ldcs((const float4*)(giB + (size_t)(512 + j) * BATCH + b0 + 4 * bi));
    }

    for (int t = 0; t < T_STEPS; t++) {
        float sR[4] = {0.f, 0.f, 0.f, 0.f};
        float sZ[4] = {0.f, 0.f, 0.f, 0.f};
        float sN[4] = {0.f, 0.f, 0.f, 0.f};

        if (t > 0) {
            // ---- fill h_s (permuted rows) from g_hs[t-1] ----
            const float4* src = (const float4*)(g_hs +
                                ((size_t)(t - 1) * BATCH + b0 + fsrc) * HID) + fk * 8;
            float4 v[8];
#pragma unroll
            for (int kk = 0; kk < 8; kk++) v[kk] = __ldcg(src + kk);
#pragma unroll
            for (int kk = 0; kk < 8; kk++)
                *(float4*)(h_s + frow * HSTRIDE + fk * 32 + kk * 4) = v[kk];
            __syncthreads();

            // ---- GEMM half-K: 3 gates x 4 batches, f32x2 over K ----
            unsigned long long aR[4] = {0, 0, 0, 0};
            unsigned long long aZ[4] = {0, 0, 0, 0};
            unsigned long long aN[4] = {0, 0, 0, 0};
#pragma unroll 4
            for (int k4 = 0; k4 < 32; k4++) {
                const float* wp = wbase + k4 * 192;
                ulonglong2 wR = *(const ulonglong2*)(wp);
                ulonglong2 wZ = *(const ulonglong2*)(wp + 64);
                ulonglong2 wN = *(const ulonglong2*)(wp + 128);
                ulonglong2 h0 = *(const ulonglong2*)(hb0 + k4 * 4);
                ulonglong2 h1 = *(const ulonglong2*)(hb1 + k4 * 4);
                ulonglong2 h2 = *(const ulonglong2*)(hb2 + k4 * 4);
                ulonglong2 h3 = *(const ulonglong2*)(hb3 + k4 * 4);
                ffma2(aR[0], wR.x, h0.x); ffma2(aR[0], wR.y, h0.y);
                ffma2(aZ[0], wZ.x, h0.x); ffma2(aZ[0], wZ.y, h0.y);
                ffma2(aN[0], wN.x, h0.x); ffma2(aN[0], wN.y, h0.y);
                ffma2(aR[1], wR.x, h1.x); ffma2(aR[1], wR.y, h1.y);
                ffma2(aZ[1], wZ.x, h1.x); ffma2(aZ[1], wZ.y, h1.y);
                ffma2(aN[1], wN.x, h1.x); ffma2(aN[1], wN.y, h1.y);
                ffma2(aR[2], wR.x, h2.x); ffma2(aR[2], wR.y, h2.y);
                ffma2(aZ[2], wZ.x, h2.x); ffma2(aZ[2], wZ.y, h2.y);
                ffma2(aN[2], wN.x, h2.x); ffma2(aN[2], wN.y, h2.y);
                ffma2(aR[3], wR.x, h3.x); ffma2(aR[3], wR.y, h3.y);
                ffma2(aZ[3], wZ.x, h3.x); ffma2(aZ[3], wZ.y, h3.y);
                ffma2(aN[3], wN.x, h3.x); ffma2(aN[3], wN.y, h3.y);
            }
#pragma unroll
            for (int m = 0; m < 4; m++) {
                float2 a = upk(aR[m]); sR[m] = a.x + a.y;
                float2 b = upk(aZ[m]); sZ[m] = b.x + b.y;
                float2 c = upk(aN[m]); sN[m] = c.x + c.y;
            }

            // ---- split-K reduction through SMEM ----
            if (kh == 1) {
                const int idx = tid - 128;
#pragma unroll
                for (int m = 0; m < 4; m++) {
                    red_s[(m * 3 + 0) * 132 + idx] = sR[m];
                    red_s[(m * 3 + 1) * 132 + idx] = sZ[m];
                    red_s[(m * 3 + 2) * 132 + idx] = sN[m];
                }
            }
            __syncthreads();
            if (kh == 0) {
#pragma unroll
                for (int m = 0; m < 4; m++) {
                    sR[m] += red_s[(m * 3 + 0) * 132 + tid];
                    sZ[m] += red_s[(m * 3 + 1) * 132 + tid];
                    sN[m] += red_s[(m * 3 + 2) * 132 + tid];
                }
            }
        }

        // ---- combine + store (kh=0 threads) ----
        if (kh == 0) {
            float giRv[4] = {gir.x, gir.y, gir.z, gir.w};
            float giZv[4] = {giz.x, giz.y, giz.z, giz.w};
            float giNv[4] = {gin.x, gin.y, gin.z, gin.w};
            float* hsT = g_hs + (size_t)t * BATCH * HID;
#pragma unroll
            for (int m = 0; m < 4; m++) {
                int b = b0 + 4 * bi + m;
                float rg = sigm(giRv[m] + sR[m] + br);
                float zg = sigm(giZv[m] + sZ[m] + bz);
                float ng = fast_tanh(giNv[m] + rg * (sN[m] + bn));
                float hp_ = (t == 0) ? 0.0f : h_s[(m * 8 + bi) * HSTRIDE + j];
                float hnew = (1.0f - zg) * ng + zg * hp_;
                __stcg(hsT + (size_t)b * HID + j, hnew);
            }
        }

        if (t + 1 < T_STEPS) {
            __threadfence();
            __syncthreads();
            if (tid == 0)
                asm volatile("red.release.gpu.global.add.u32 [%0], %1;"
                             :: "l"(cnt), "r"(1u) : "memory");

            if (kh == 0) {
                const float* giN = g_gi + (size_t)(t + 1) * G3 * BATCH;
                gir = __ldcs((const float4*)(giN + (size_t)j * BATCH + b0 + 4 * bi));
                giz = __ldcs((const float4*)(giN + (size_t)(256 + j) * BATCH + b0 + 4 * bi));
                gin = __ldcs((const float4*)(giN + (size_t)(512 + j) * BATCH + b0 + 4 * bi));
            }

            if (tid == 0) {
                const unsigned tgt = 16u * (unsigned)(t + 1);
                unsigned v;
                do {
                    asm volatile("ld.acquire.gpu.global.u32 %0, [%1];"
                                 : "=r"(v) : "l"(cnt) : "memory");
                } while (v < tgt);
            }
            __syncthreads();
        }
    }
}

// ---------------- phase 2: out[t*256+b] = dot(hs[t][b][:], w_out) + b_out ----------------
__global__ void __launch_bounds__(256) out_kernel(
    const float* __restrict__ w_out, const float* __restrict__ b_out,
    float* __restrict__ out) {
    __shared__ __align__(16) float wsm[256];
    const int tid = threadIdx.x;
    wsm[tid] = w_out[tid];
    __syncthreads();

    const int warp = tid >> 5, lane = tid & 31;
    const size_t gid = (size_t)blockIdx.x * 8 + warp;
    const float* hrow = g_hs + gid * HID;

    float s = 0.0f;
#pragma unroll
    for (int kk = 0; kk < 2; kk++) {
        int k4 = lane + 32 * kk;
        float4 h = *(const float4*)(hrow + k4 * 4);
        float4 w = *(const float4*)(wsm + k4 * 4);
        s += h.x * w.x + h.y * w.y + h.z * w.z + h.w * w.w;
    }
#pragma unroll
    for (int o = 16; o; o >>= 1) s += __shfl_down_sync(0xffffffffu, s, o);
    if (lane == 0) out[gid] = s + __ldg(b_out);
}

// ---------------- launch ----------------
extern "C" void kernel_launch(void* const* d_in, const int* in_sizes, int n_in,
                              void* d_out, int out_size) {
    const float* x     = (const float*)d_in[0];
    const float* w_ih  = (const float*)d_in[1];
    const float* w_hh  = (const float*)d_in[2];
    const float* b_ih  = (const float*)d_in[3];
    const float* b_hh  = (const float*)d_in[4];
    const float* w_out = (const float*)d_in[5];
    const float* b_out = (const float*)d_in[6];
    float* out = (float*)d_out;

    const int smem_proj = 64 * 132 * 2 * sizeof(float);
    const int smem_rec  = (64 * 3 * 16 * 4 + 32 * HSTRIDE + 12 * 132) * sizeof(float);
    cudaFuncSetAttribute(input_proj_kernel,
        cudaFuncAttributeMaxDynamicSharedMemorySize, smem_proj);
    cudaFuncSetAttribute(gru_rec_kernel,
        cudaFuncAttributeMaxDynamicSharedMemorySize, smem_rec);

    reset_kernel<<<1, 256>>>();
    input_proj_kernel<<<dim3(512, 6, 2), 256, smem_proj>>>(x, w_ih, b_ih);
    gru_rec_kernel<<<dim3(16, 8), 256, smem_rec>>>(w_hh, b_hh);
    out_kernel<<<16384, 256>>>(w_out, b_out, out);
}

// round 10
// speedup vs baseline: 2.6803x; 1.0417x over previous
#include <cuda_runtime.h>

#define T_STEPS 512
#define BATCH   256
#define HID     256
#define G3      768   // 3*HID

// ---------------- static scratch (no allocations allowed) ----------------
__device__ float    g_gi[(size_t)T_STEPS * G3 * BATCH];    // [t][g][b]
__device__ float    g_hs[(size_t)T_STEPS * BATCH * HID];   // [t][b][j]
__device__ unsigned g_cnt[8][32];                          // 1 counter/group, 128B apart

// ---------------- helpers ----------------
__device__ __forceinline__ void ffma2(unsigned long long& d,
                                      unsigned long long a,
                                      unsigned long long b) {
    asm("fma.rn.f32x2 %0, %1, %2, %0;" : "+l"(d) : "l"(a), "l"(b));
}
__device__ __forceinline__ unsigned long long pk2(float s) {
    unsigned long long d;
    asm("mov.b64 %0, {%1,%1};" : "=l"(d) : "f"(s));
    return d;
}
__device__ __forceinline__ float2 upk(unsigned long long v) {
    float2 f;
    asm("mov.b64 {%0,%1}, %2;" : "=f"(f.x), "=f"(f.y) : "l"(v));
    return f;
}
__device__ __forceinline__ float sigm(float x) {
    return 1.0f / (1.0f + __expf(-x));
}
__device__ __forceinline__ float fast_tanh(float x) {
    float e = __expf(2.0f * x);
    return 1.0f - __fdividef(2.0f, e + 1.0f);
}

// ---------------- reset counters ----------------
__global__ void reset_kernel() {
    if (threadIdx.x < 8 * 32) ((unsigned*)g_cnt)[threadIdx.x] = 0u;
}

// ---------------- phase 0: gi[t][g][b] = sum_i w_ih[g][i]*x[b][t][i] + b_ih[g] ----------------
__global__ void __launch_bounds__(256) input_proj_kernel(
    const float* __restrict__ x, const float* __restrict__ w_ih,
    const float* __restrict__ b_ih) {
    extern __shared__ float sm[];
    float* wsm = sm;              // wsm[i*132 + g_local]
    float* xsm = sm + 64 * 132;   // xsm[i*132 + b_local]

    const int t  = blockIdx.x;
    const int g0 = blockIdx.y * 128;
    const int b0 = blockIdx.z * 128;
    const int tid = threadIdx.x;

#pragma unroll
    for (int it = 0; it < 8; it++) {
        int f  = tid + 256 * it;
        int gg = f >> 4, i4 = f & 15;
        float4 v = *(const float4*)(w_ih + (size_t)(g0 + gg) * 64 + i4 * 4);
        wsm[(i4 * 4 + 0) * 132 + gg] = v.x;
        wsm[(i4 * 4 + 1) * 132 + gg] = v.y;
        wsm[(i4 * 4 + 2) * 132 + gg] = v.z;
        wsm[(i4 * 4 + 3) * 132 + gg] = v.w;
    }
#pragma unroll
    for (int it = 0; it < 8; it++) {
        int f  = tid + 256 * it;
        int bb = f >> 4, i4 = f & 15;
        float4 v = *(const float4*)(x + ((size_t)(b0 + bb) * T_STEPS + t) * 64 + i4 * 4);
        xsm[(i4 * 4 + 0) * 132 + bb] = v.x;
        xsm[(i4 * 4 + 1) * 132 + bb] = v.y;
        xsm[(i4 * 4 + 2) * 132 + bb] = v.z;
        xsm[(i4 * 4 + 3) * 132 + bb] = v.w;
    }
    __syncthreads();

    const int tg = tid & 15, tb = tid >> 4;
    const int gl = tg * 8, bl = tb * 8;

    unsigned long long acc[32];
#pragma unroll
    for (int i = 0; i < 32; i++) acc[i] = 0ULL;

#pragma unroll 2
    for (int k = 0; k < 64; k++) {
        float4 wa = *(const float4*)(wsm + k * 132 + gl);
        float4 wb = *(const float4*)(wsm + k * 132 + gl + 4);
        ulonglong2 x01 = *(const ulonglong2*)(xsm + k * 132 + bl);
        ulonglong2 x23 = *(const ulonglong2*)(xsm + k * 132 + bl + 4);
        float wr[8] = {wa.x, wa.y, wa.z, wa.w, wb.x, wb.y, wb.z, wb.w};
#pragma unroll
        for (int gg = 0; gg < 8; gg++) {
            unsigned long long wd = pk2(wr[gg]);
            ffma2(acc[gg * 4 + 0], wd, x01.x);
            ffma2(acc[gg * 4 + 1], wd, x01.y);
            ffma2(acc[gg * 4 + 2], wd, x23.x);
            ffma2(acc[gg * 4 + 3], wd, x23.y);
        }
    }

#pragma unroll
    for (int gg = 0; gg < 8; gg++) {
        float bias = __ldg(b_ih + g0 + gl + gg);
        float2 p0 = upk(acc[gg * 4 + 0]);
        float2 p1 = upk(acc[gg * 4 + 1]);
        float2 p2 = upk(acc[gg * 4 + 2]);
        float2 p3 = upk(acc[gg * 4 + 3]);
        float* o = g_gi + ((size_t)t * G3 + (g0 + gl + gg)) * BATCH + b0 + bl;
        *(float4*)o       = make_float4(p0.x + bias, p0.y + bias, p1.x + bias, p1.y + bias);
        *(float4*)(o + 4) = make_float4(p2.x + bias, p2.y + bias, p3.x + bias, p3.y + bias);
    }
}

// ---------------- phase 1: persistent GRU recurrence ----------------
// grid (16 jt, 8 grp), block 256 = (rg 0..7)x(bg 0..3)x(kc 0..7).
// Thread tile: 6 gate-rows (rows 6rg..6rg+5; row = jloc*3+gate) x 8 batches
// (b = 4m+bg) x 32 k (k4 = kc+8i, interleaved -> conflict-free LDS.128).
// 8-way split-K reduced through padded SMEM; combine on tid<128.
#define HSTRIDE 260
#define RSLICE  1732   // floats per kc reduction slice (48*36 + pad4)

__global__ void __launch_bounds__(256) gru_rec_kernel(
    const float* __restrict__ w_hh, const float* __restrict__ b_hh) {
    extern __shared__ float sm[];
    float* w_il  = sm;                       // [48][256]       48 KB
    float* h_s   = sm + 48 * 256;            // [32][HSTRIDE]   33.3 KB
    float* red_s = h_s + 32 * HSTRIDE;       // [8][RSLICE]     55.4 KB

    const int tid = threadIdx.x;
    const int rg  = tid >> 5;               // warp: row group (6 rows)
    const int bg  = (tid >> 3) & 3;         // batch phase
    const int kc  = tid & 7;                // k chunk (interleaved)
    const int jt  = blockIdx.x;
    const int grp = blockIdx.y;
    const int b0  = grp * 32;
    const int j0  = jt * 16;

    // ---- preload weights: w_il[row][k], row = jloc*3 + gate ----
#pragma unroll
    for (int it = 0; it < 12; it++) {
        int f4 = tid + 256 * it;             // 0..3071 float4 slots
        int row = f4 >> 6, k4 = f4 & 63;
        int jloc = row / 3, g = row - 3 * jloc;
        float4 v = __ldg((const float4*)(w_hh +
                     ((size_t)(g * 256 + j0 + jloc)) * 256 + k4 * 4));
        *(float4*)(w_il + row * 256 + k4 * 4) = v;
    }
    __syncthreads();

    // combine-role constants (tid < 128): jloc = tid&15, bi = tid>>4
    const int c_jl = tid & 15;
    const int c_bi = tid >> 4;              // 0..7
    const int c_j  = j0 + c_jl;
    float br = 0.f, bz = 0.f, bn = 0.f;
    if (tid < 128) {
        br = __ldg(b_hh + c_j);
        bz = __ldg(b_hh + 256 + c_j);
        bn = __ldg(b_hh + 512 + c_j);
    }

    const int frow = tid & 31;              // fill row (batch)
    const int fkq  = tid >> 5;              // fill k-quarter (8 float4)

    unsigned* cnt = &g_cnt[grp][0];

    // prefetch gi(0)
    float4 gir, giz, gin;
    if (tid < 128) {
        const float* giB = g_gi;
        gir = __ldcs((const float4*)(giB + (size_t)c_j * BATCH + b0 + 4 * c_bi));
        giz = __ldcs((const float4*)(giB + (size_t)(256 + c_j) * BATCH + b0 + 4 * c_bi));
        gin = __ldcs((const float4*)(giB + (size_t)(512 + c_j) * BATCH + b0 + 4 * c_bi));
    }

    const float* wrow = w_il + (6 * rg) * 256;

    for (int t = 0; t < T_STEPS; t++) {
        if (t > 0) {
            // ---- fill h_s[b][k] from g_hs[t-1] ----
            const float4* src = (const float4*)(g_hs +
                                ((size_t)(t - 1) * BATCH + b0 + frow) * HID) + fkq * 8;
            float4 v[8];
#pragma unroll
            for (int kk = 0; kk < 8; kk++) v[kk] = __ldcg(src + kk);
#pragma unroll
            for (int kk = 0; kk < 8; kk++)
                *(float4*)(h_s + frow * HSTRIDE + fkq * 32 + kk * 4) = v[kk];
            __syncthreads();

            // ---- GEMM: 6 rows x 8 batches x 32 k per thread ----
            unsigned long long acc[6][8];
#pragma unroll
            for (int r = 0; r < 6; r++)
#pragma unroll
                for (int m = 0; m < 8; m++) acc[r][m] = 0ULL;

#pragma unroll
            for (int i = 0; i < 8; i++) {
                const int k4 = kc + 8 * i;
                ulonglong2 wv[6];
#pragma unroll
                for (int r = 0; r < 6; r++)
                    wv[r] = *(const ulonglong2*)(wrow + r * 256 + k4 * 4);
#pragma unroll
                for (int m = 0; m < 8; m++) {
                    ulonglong2 hv = *(const ulonglong2*)
                        (h_s + (4 * m + bg) * HSTRIDE + k4 * 4);
#pragma unroll
                    for (int r = 0; r < 6; r++) {
                        ffma2(acc[r][m], wv[r].x, hv.x);
                        ffma2(acc[r][m], wv[r].y, hv.y);
                    }
                }
            }

            // ---- write partials: red_s[kc][row*36 + b] ----
            float* rs = red_s + kc * RSLICE + (6 * rg) * 36 + bg;
#pragma unroll
            for (int r = 0; r < 6; r++)
#pragma unroll
                for (int m = 0; m < 8; m++) {
                    float2 p = upk(acc[r][m]);
                    rs[r * 36 + 4 * m] = p.x + p.y;
                }
            __syncthreads();
        }

        // ---- combine (tid < 128): sum 8 kc partials, gates, store h ----
        if (tid < 128) {
            float4 sR = make_float4(0.f, 0.f, 0.f, 0.f);
            float4 sZ = sR, sN = sR;
            if (t > 0) {
                const int rowR = (c_jl * 3 + 0) * 36 + 4 * c_bi;
                const int rowZ = (c_jl * 3 + 1) * 36 + 4 * c_bi;
                const int rowN = (c_jl * 3 + 2) * 36 + 4 * c_bi;
#pragma unroll
                for (int k = 0; k < 8; k++) {
                    const float* rp = red_s + k * RSLICE;
                    float4 a = *(const float4*)(rp + rowR);
                    float4 b = *(const float4*)(rp + rowZ);
                    float4 c = *(const float4*)(rp + rowN);
                    sR.x += a.x; sR.y += a.y; sR.z += a.z; sR.w += a.w;
                    sZ.x += b.x; sZ.y += b.y; sZ.z += b.z; sZ.w += b.w;
                    sN.x += c.x; sN.y += c.y; sN.z += c.z; sN.w += c.w;
                }
            }
            float sRa[4] = {sR.x, sR.y, sR.z, sR.w};
            float sZa[4] = {sZ.x, sZ.y, sZ.z, sZ.w};
            float sNa[4] = {sN.x, sN.y, sN.z, sN.w};
            float giRv[4] = {gir.x, gir.y, gir.z, gir.w};
            float giZv[4] = {giz.x, giz.y, giz.z, giz.w};
            float giNv[4] = {gin.x, gin.y, gin.z, gin.w};
            float* hsT = g_hs + (size_t)t * BATCH * HID;
#pragma unroll
            for (int m = 0; m < 4; m++) {
                int b = b0 + 4 * c_bi + m;
                float rgt = sigm(giRv[m] + sRa[m] + br);
                float zg = sigm(giZv[m] + sZa[m] + bz);
                float ng = fast_tanh(giNv[m] + rgt * (sNa[m] + bn));
                float hp_ = (t == 0) ? 0.0f
                          : h_s[(4 * c_bi + m) * HSTRIDE + c_j];
                float hnew = (1.0f - zg) * ng + zg * hp_;
                __stcg(hsT + (size_t)b * HID + c_j, hnew);
            }
        }

        if (t + 1 < T_STEPS) {
            __threadfence();
            __syncthreads();
            if (tid == 0)
                asm volatile("red.release.gpu.global.add.u32 [%0], %1;"
                             :: "l"(cnt), "r"(1u) : "memory");

            if (tid < 128) {
                const float* giN = g_gi + (size_t)(t + 1) * G3 * BATCH;
                gir = __ldcs((const float4*)(giN + (size_t)c_j * BATCH + b0 + 4 * c_bi));
                giz = __ldcs((const float4*)(giN + (size_t)(256 + c_j) * BATCH + b0 + 4 * c_bi));
                gin = __ldcs((const float4*)(giN + (size_t)(512 + c_j) * BATCH + b0 + 4 * c_bi));
            }

            if (tid == 0) {
                const unsigned tgt = 16u * (unsigned)(t + 1);
                unsigned v;
                do {
                    asm volatile("ld.acquire.gpu.global.u32 %0, [%1];"
                                 : "=r"(v) : "l"(cnt) : "memory");
                } while (v < tgt);
            }
            __syncthreads();
        }
    }
}

// ---------------- phase 2: out[t*256+b] = dot(hs[t][b][:], w_out) + b_out ----------------
__global__ void __launch_bounds__(256) out_kernel(
    const float* __restrict__ w_out, const float* __restrict__ b_out,
    float* __restrict__ out) {
    __shared__ __align__(16) float wsm[256];
    const int tid = threadIdx.x;
    wsm[tid] = w_out[tid];
    __syncthreads();

    const int warp = tid >> 5, lane = tid & 31;
    const size_t gid = (size_t)blockIdx.x * 8 + warp;
    const float* hrow = g_hs + gid * HID;

    float s = 0.0f;
#pragma unroll
    for (int kk = 0; kk < 2; kk++) {
        int k4 = lane + 32 * kk;
        float4 h = *(const float4*)(hrow + k4 * 4);
        float4 w = *(const float4*)(wsm + k4 * 4);
        s += h.x * w.x + h.y * w.y + h.z * w.z + h.w * w.w;
    }
#pragma unroll
    for (int o = 16; o; o >>= 1) s += __shfl_down_sync(0xffffffffu, s, o);
    if (lane == 0) out[gid] = s + __ldg(b_out);
}

// ---------------- launch ----------------
extern "C" void kernel_launch(void* const* d_in, const int* in_sizes, int n_in,
                              void* d_out, int out_size) {
    const float* x     = (const float*)d_in[0];
    const float* w_ih  = (const float*)d_in[1];
    const float* w_hh  = (const float*)d_in[2];
    const float* b_ih  = (const float*)d_in[3];
    const float* b_hh  = (const float*)d_in[4];
    const float* w_out = (const float*)d_in[5];
    const float* b_out = (const float*)d_in[6];
    float* out = (float*)d_out;

    const int smem_proj = 64 * 132 * 2 * sizeof(float);
    const int smem_rec  = (48 * 256 + 32 * HSTRIDE + 8 * RSLICE) * sizeof(float);
    cudaFuncSetAttribute(input_proj_kernel,
        cudaFuncAttributeMaxDynamicSharedMemorySize, smem_proj);
    cudaFuncSetAttribute(gru_rec_kernel,
        cudaFuncAttributeMaxDynamicSharedMemorySize, smem_rec);

    reset_kernel<<<1, 256>>>();
    input_proj_kernel<<<dim3(512, 6, 2), 256, smem_proj>>>(x, w_ih, b_ih);
    gru_rec_kernel<<<dim3(16, 8), 256, smem_rec>>>(w_hh, b_hh);
    out_kernel<<<16384, 256>>>(w_out, b_out, out);
}

// round 11
// speedup vs baseline: 3.0119x; 1.1237x over previous
#include <cuda_runtime.h>

#define T_STEPS 512
#define BATCH   256
#define HID     256
#define G3      768   // 3*HID

#define J_TILE  32    // hidden units per block
#define B_TILE  16    // batch rows per block
#define NGRP    16    // batch groups
#define NJT     8     // j-tiles
#define CHUNK   64    // steps per launch

// ---------------- static scratch (no allocations allowed) ----------------
__device__ float    g_gi[(size_t)T_STEPS * G3 * BATCH];    // [t][g][b]
__device__ float    g_hs[(size_t)T_STEPS * BATCH * HID];   // [t][b][j]
__device__ unsigned g_cnt[NGRP][32];                       // 1 counter/group, 128B apart

// ---------------- helpers ----------------
__device__ __forceinline__ void ffma2(unsigned long long& d,
                                      unsigned long long a,
                                      unsigned long long b) {
    asm("fma.rn.f32x2 %0, %1, %2, %0;" : "+l"(d) : "l"(a), "l"(b));
}
__device__ __forceinline__ unsigned long long pk2(float s) {
    unsigned long long d;
    asm("mov.b64 %0, {%1,%1};" : "=l"(d) : "f"(s));
    return d;
}
__device__ __forceinline__ float2 upk(unsigned long long v) {
    float2 f;
    asm("mov.b64 {%0,%1}, %2;" : "=f"(f.x), "=f"(f.y) : "l"(v));
    return f;
}
__device__ __forceinline__ float sigm(float x) {
    return 1.0f / (1.0f + __expf(-x));
}
__device__ __forceinline__ float fast_tanh(float x) {
    float e = __expf(2.0f * x);
    return 1.0f - __fdividef(2.0f, e + 1.0f);
}

// ---------------- reset counters ----------------
__global__ void reset_kernel() {
    if (threadIdx.x < NGRP * 32) ((unsigned*)g_cnt)[threadIdx.x] = 0u;
}

// ---------------- phase 0: gi[t][g][b] = sum_i w_ih[g][i]*x[b][t][i] + b_ih[g] ----------------
__global__ void __launch_bounds__(256) input_proj_kernel(
    const float* __restrict__ x, const float* __restrict__ w_ih,
    const float* __restrict__ b_ih) {
    extern __shared__ float sm[];
    float* wsm = sm;              // wsm[i*132 + g_local]
    float* xsm = sm + 64 * 132;   // xsm[i*132 + b_local]

    const int t  = blockIdx.x;
    const int g0 = blockIdx.y * 128;
    const int b0 = blockIdx.z * 128;
    const int tid = threadIdx.x;

#pragma unroll
    for (int it = 0; it < 8; it++) {
        int f  = tid + 256 * it;
        int gg = f >> 4, i4 = f & 15;
        float4 v = *(const float4*)(w_ih + (size_t)(g0 + gg) * 64 + i4 * 4);
        wsm[(i4 * 4 + 0) * 132 + gg] = v.x;
        wsm[(i4 * 4 + 1) * 132 + gg] = v.y;
        wsm[(i4 * 4 + 2) * 132 + gg] = v.z;
        wsm[(i4 * 4 + 3) * 132 + gg] = v.w;
    }
#pragma unroll
    for (int it = 0; it < 8; it++) {
        int f  = tid + 256 * it;
        int bb = f >> 4, i4 = f & 15;
        float4 v = *(const float4*)(x + ((size_t)(b0 + bb) * T_STEPS + t) * 64 + i4 * 4);
        xsm[(i4 * 4 + 0) * 132 + bb] = v.x;
        xsm[(i4 * 4 + 1) * 132 + bb] = v.y;
        xsm[(i4 * 4 + 2) * 132 + bb] = v.z;
        xsm[(i4 * 4 + 3) * 132 + bb] = v.w;
    }
    __syncthreads();

    const int tg = tid & 15, tb = tid >> 4;
    const int gl = tg * 8, bl = tb * 8;

    unsigned long long acc[32];
#pragma unroll
    for (int i = 0; i < 32; i++) acc[i] = 0ULL;

#pragma unroll 2
    for (int k = 0; k < 64; k++) {
        float4 wa = *(const float4*)(wsm + k * 132 + gl);
        float4 wb = *(const float4*)(wsm + k * 132 + gl + 4);
        ulonglong2 x01 = *(const ulonglong2*)(xsm + k * 132 + bl);
        ulonglong2 x23 = *(const ulonglong2*)(xsm + k * 132 + bl + 4);
        float wr[8] = {wa.x, wa.y, wa.z, wa.w, wb.x, wb.y, wb.z, wb.w};
#pragma unroll
        for (int gg = 0; gg < 8; gg++) {
            unsigned long long wd = pk2(wr[gg]);
            ffma2(acc[gg * 4 + 0], wd, x01.x);
            ffma2(acc[gg * 4 + 1], wd, x01.y);
            ffma2(acc[gg * 4 + 2], wd, x23.x);
            ffma2(acc[gg * 4 + 3], wd, x23.y);
        }
    }

#pragma unroll
    for (int gg = 0; gg < 8; gg++) {
        float bias = __ldg(b_ih + g0 + gl + gg);
        float2 p0 = upk(acc[gg * 4 + 0]);
        float2 p1 = upk(acc[gg * 4 + 1]);
        float2 p2 = upk(acc[gg * 4 + 2]);
        float2 p3 = upk(acc[gg * 4 + 3]);
        float* o = g_gi + ((size_t)t * G3 + (g0 + gl + gg)) * BATCH + b0 + bl;
        *(float4*)o       = make_float4(p0.x + bias, p0.y + bias, p1.x + bias, p1.y + bias);
        *(float4*)(o + 4) = make_float4(p2.x + bias, p2.y + bias, p3.x + bias, p3.y + bias);
    }
}

// ---------------- phase 1: GRU recurrence, chunked ----------------
// grid (8 jt, 16 grp), block 256 = (rg 0..15)x(bg 0..1)x(kc 0..7).
// Block: j-tile 32 (rows 96 = jloc*3+gate), batch tile 16.
// Thread tile: 6 rows (6rg..6rg+5) x 8 batches (b = 2m+bg) x 32 k (k4 = kc+8i).
// kc-reduction: in-warp butterfly shuffle (lanes bg*8+kc adjacent) -> lane kc
// keeps m == kc. Tiny red_s only for (warp -> combine-thread) handoff.
#define HSTRIDE 260
#define RPITCH  20

__global__ void __launch_bounds__(256) gru_rec_kernel(
    const float* __restrict__ w_hh, const float* __restrict__ b_hh,
    int chunk) {
    extern __shared__ float sm[];
    float* w_il  = sm;                        // [96][256]   96 KB
    float* h_s   = sm + 96 * 256;             // [16][260]   16.6 KB
    float* red_s = h_s + 16 * HSTRIDE;        // [96][20]    7.5 KB

    const int tid = threadIdx.x;
    const int rg  = tid >> 4;                 // 0..15 row group (6 rows)
    const int bg  = (tid >> 3) & 1;           // batch parity
    const int kc  = tid & 7;                  // k chunk
    const int jt  = blockIdx.x;               // 0..7
    const int grp = blockIdx.y;               // 0..15
    const int b0  = grp * B_TILE;
    const int j0  = jt * J_TILE;

    // ---- preload weights: w_il[row][k], row = jloc*3 + gate (96 rows) ----
#pragma unroll
    for (int it = 0; it < 24; it++) {
        int f4 = tid + 256 * it;              // 0..6143 float4 slots
        int row = f4 >> 6, k4 = f4 & 63;
        int jloc = row / 3, g = row - 3 * jloc;
        float4 v = __ldg((const float4*)(w_hh +
                     ((size_t)(g * 256 + j0 + jloc)) * 256 + k4 * 4));
        *(float4*)(w_il + row * 256 + k4 * 4) = v;
    }
    __syncthreads();

    // combine-role constants (tid < 128): jloc = tid&31, bq = tid>>5 (0..3)
    const int c_jl = tid & 31;
    const int c_bq = tid >> 5;
    const int c_j  = j0 + c_jl;
    float br = 0.f, bz = 0.f, bn = 0.f;
    if (tid < 128) {
        br = __ldg(b_hh + c_j);
        bz = __ldg(b_hh + 256 + c_j);
        bn = __ldg(b_hh + 512 + c_j);
    }

    const int frow = tid & 15;                // fill: batch row
    const int fq   = tid >> 4;                // fill: 4-float4 quarter

    unsigned* cnt = &g_cnt[grp][0];
    const int t0 = chunk * CHUNK;

    // prefetch gi(t0)
    float4 gir, giz, gin;
    if (tid < 128) {
        const float* giB = g_gi + (size_t)t0 * G3 * BATCH;
        gir = __ldcs((const float4*)(giB + (size_t)c_j * BATCH + b0 + 4 * c_bq));
        giz = __ldcs((const float4*)(giB + (size_t)(256 + c_j) * BATCH + b0 + 4 * c_bq));
        gin = __ldcs((const float4*)(giB + (size_t)(512 + c_j) * BATCH + b0 + 4 * c_bq));
    }

    const float* wrow = w_il + (6 * rg) * 256;

    for (int tl = 0; tl < CHUNK; tl++) {
        const int t = t0 + tl;
        float s2[6];
#pragma unroll
        for (int r = 0; r < 6; r++) s2[r] = 0.0f;

        if (t > 0) {
            // ---- fill h_s[b][k] from g_hs[t-1]: 16 rows x 256 ----
            const float4* src = (const float4*)(g_hs +
                                ((size_t)(t - 1) * BATCH + b0 + frow) * HID) + fq * 4;
            float4 v[4];
#pragma unroll
            for (int kk = 0; kk < 4; kk++) v[kk] = __ldcg(src + kk);
#pragma unroll
            for (int kk = 0; kk < 4; kk++)
                *(float4*)(h_s + frow * HSTRIDE + fq * 16 + kk * 4) = v[kk];
            __syncthreads();

            // ---- GEMM: 6 rows x 8 batches x 32 k4/8 per thread ----
            unsigned long long acc[6][8];
#pragma unroll
            for (int r = 0; r < 6; r++)
#pragma unroll
                for (int m = 0; m < 8; m++) acc[r][m] = 0ULL;

#pragma unroll
            for (int i = 0; i < 8; i++) {
                const int k4 = kc + 8 * i;
                ulonglong2 wv[6];
#pragma unroll
                for (int r = 0; r < 6; r++)
                    wv[r] = *(const ulonglong2*)(wrow + r * 256 + k4 * 4);
#pragma unroll
                for (int m = 0; m < 8; m++) {
                    ulonglong2 hv = *(const ulonglong2*)
                        (h_s + (2 * m + bg) * HSTRIDE + k4 * 4);
#pragma unroll
                    for (int r = 0; r < 6; r++) {
                        ffma2(acc[r][m], wv[r].x, hv.x);
                        ffma2(acc[r][m], wv[r].y, hv.y);
                    }
                }
            }

            // ---- fold f32x2 + butterfly kc-reduction with redistribution ----
            float s0[6][8];
#pragma unroll
            for (int r = 0; r < 6; r++)
#pragma unroll
                for (int m = 0; m < 8; m++) {
                    float2 p = upk(acc[r][m]);
                    s0[r][m] = p.x + p.y;
                }
            // round 0 (mask 1): keep m with bit0 == kc bit0
            float s1[6][4];
            {
                bool hi = kc & 1;
#pragma unroll
                for (int r = 0; r < 6; r++)
#pragma unroll
                    for (int q = 0; q < 4; q++) {
                        float mine   = hi ? s0[r][2 * q + 1] : s0[r][2 * q];
                        float theirs = hi ? s0[r][2 * q]     : s0[r][2 * q + 1];
                        s1[r][q] = mine + __shfl_xor_sync(0xffffffffu, theirs, 1);
                    }
            }
            // round 1 (mask 2)
            float s1b[6][2];
            {
                bool hi = (kc >> 1) & 1;
#pragma unroll
                for (int r = 0; r < 6; r++)
#pragma unroll
                    for (int q = 0; q < 2; q++) {
                        float mine   = hi ? s1[r][2 * q + 1] : s1[r][2 * q];
                        float theirs = hi ? s1[r][2 * q]     : s1[r][2 * q + 1];
                        s1b[r][q] = mine + __shfl_xor_sync(0xffffffffu, theirs, 2);
                    }
            }
            // round 2 (mask 4) -> lane kc holds m == kc
            {
                bool hi = (kc >> 2) & 1;
#pragma unroll
                for (int r = 0; r < 6; r++) {
                    float mine   = hi ? s1b[r][1] : s1b[r][0];
                    float theirs = hi ? s1b[r][0] : s1b[r][1];
                    s2[r] = mine + __shfl_xor_sync(0xffffffffu, theirs, 4);
                }
            }
            // ---- handoff: red_s[row][bb], bb = 2*kc + bg ----
            float* rs = red_s + (2 * kc + bg);
#pragma unroll
            for (int r = 0; r < 6; r++)
                rs[(6 * rg + r) * RPITCH] = s2[r];
            __syncthreads();
        }

        // ---- combine (tid < 128): 1 j x 4 batches each ----
        if (tid < 128) {
            float4 sR = make_float4(0.f, 0.f, 0.f, 0.f);
            float4 sZ = sR, sN = sR;
            if (t > 0) {
                sR = *(const float4*)(red_s + (3 * c_jl + 0) * RPITCH + 4 * c_bq);
                sZ = *(const float4*)(red_s + (3 * c_jl + 1) * RPITCH + 4 * c_bq);
                sN = *(const float4*)(red_s + (3 * c_jl + 2) * RPITCH + 4 * c_bq);
            }
            float sRa[4] = {sR.x, sR.y, sR.z, sR.w};
            float sZa[4] = {sZ.x, sZ.y, sZ.z, sZ.w};
            float sNa[4] = {sN.x, sN.y, sN.z, sN.w};
            float giRv[4] = {gir.x, gir.y, gir.z, gir.w};
            float giZv[4] = {giz.x, giz.y, giz.z, giz.w};
            float giNv[4] = {gin.x, gin.y, gin.z, gin.w};
            float* hsT = g_hs + (size_t)t * BATCH * HID;
#pragma unroll
            for (int m = 0; m < 4; m++) {
                int bb = 4 * c_bq + m;
                float rgt = sigm(giRv[m] + sRa[m] + br);
                float zg = sigm(giZv[m] + sZa[m] + bz);
                float ng = fast_tanh(giNv[m] + rgt * (sNa[m] + bn));
                float hp_ = (t == 0) ? 0.0f : h_s[bb * HSTRIDE + c_j];
                float hnew = (1.0f - zg) * ng + zg * hp_;
                __stcg(hsT + (size_t)(b0 + bb) * HID + c_j, hnew);
            }
        }

        if (tl + 1 < CHUNK) {
            // ---- publish + barrier (8 agents per group) ----
            __threadfence();
            __syncthreads();
            if (tid == 0)
                asm volatile("red.release.gpu.global.add.u32 [%0], %1;"
                             :: "l"(cnt), "r"(1u) : "memory");

            if (tid < 128) {
                const float* giN = g_gi + (size_t)(t + 1) * G3 * BATCH;
                gir = __ldcs((const float4*)(giN + (size_t)c_j * BATCH + b0 + 4 * c_bq));
                giz = __ldcs((const float4*)(giN + (size_t)(256 + c_j) * BATCH + b0 + 4 * c_bq));
                gin = __ldcs((const float4*)(giN + (size_t)(512 + c_j) * BATCH + b0 + 4 * c_bq));
            }

            if (tid == 0) {
                const unsigned tgt = 8u * (unsigned)(chunk * (CHUNK - 1) + tl + 1);
                unsigned v;
                do {
                    asm volatile("ld.acquire.gpu.global.u32 %0, [%1];"
                                 : "=r"(v) : "l"(cnt) : "memory");
                } while (v < tgt);
            }
            __syncthreads();
        }
    }
}

// ---------------- phase 2: out[t*256+b] = dot(hs[t][b][:], w_out) + b_out ----------------
__global__ void __launch_bounds__(256) out_kernel(
    const float* __restrict__ w_out, const float* __restrict__ b_out,
    float* __restrict__ out) {
    __shared__ __align__(16) float wsm[256];
    const int tid = threadIdx.x;
    wsm[tid] = w_out[tid];
    __syncthreads();

    const int warp = tid >> 5, lane = tid & 31;
    const size_t gid = (size_t)blockIdx.x * 8 + warp;
    const float* hrow = g_hs + gid * HID;

    float s = 0.0f;
#pragma unroll
    for (int kk = 0; kk < 2; kk++) {
        int k4 = lane + 32 * kk;
        float4 h = *(const float4*)(hrow + k4 * 4);
        float4 w = *(const float4*)(wsm + k4 * 4);
        s += h.x * w.x + h.y * w.y + h.z * w.z + h.w * w.w;
    }
#pragma unroll
    for (int o = 16; o; o >>= 1) s += __shfl_down_sync(0xffffffffu, s, o);
    if (lane == 0) out[gid] = s + __ldg(b_out);
}

// ---------------- launch ----------------
extern "C" void kernel_launch(void* const* d_in, const int* in_sizes, int n_in,
                              void* d_out, int out_size) {
    const float* x     = (const float*)d_in[0];
    const float* w_ih  = (const float*)d_in[1];
    const float* w_hh  = (const float*)d_in[2];
    const float* b_ih  = (const float*)d_in[3];
    const float* b_hh  = (const float*)d_in[4];
    const float* w_out = (const float*)d_in[5];
    const float* b_out = (const float*)d_in[6];
    float* out = (float*)d_out;

    const int smem_proj = 64 * 132 * 2 * sizeof(float);
    const int smem_rec  = (96 * 256 + 16 * HSTRIDE + 96 * RPITCH) * sizeof(float);
    cudaFuncSetAttribute(input_proj_kernel,
        cudaFuncAttributeMaxDynamicSharedMemorySize, smem_proj);
    cudaFuncSetAttribute(gru_rec_kernel,
        cudaFuncAttributeMaxDynamicSharedMemorySize, smem_rec);

    reset_kernel<<<1, NGRP * 32>>>();
    input_proj_kernel<<<dim3(512, 6, 2), 256, smem_proj>>>(x, w_ih, b_ih);
    for (int c = 0; c < T_STEPS / CHUNK; c++)
        gru_rec_kernel<<<dim3(NJT, NGRP), 256, smem_rec>>>(w_hh, b_hh, c);
    out_kernel<<<16384, 256>>>(w_out, b_out, out);
}